// round 11
// baseline (speedup 1.0000x reference)
#include <cuda_runtime.h>
#include <cuda_bf16.h>
#include <math.h>
#include <stdint.h>

typedef __nv_bfloat16 bf16;

#define BB     2
#define NN     2048
#define DIM    1024
#define HH     16
#define DH     64
#define INNER  1024
#define ROWS   (BB*NN)       // 4096
#define NQKV   3072
#define KD     1024
#define LN_EPS   1e-5f
#define ATTN_EPS 1e-8f
#define SCALE    0.125f
#define SCL2E    0.1803368801111244f   // SCALE * log2(e)

// ---------------------------------------------------------------------------
// Scratch (device globals)
// ---------------------------------------------------------------------------
__device__ bf16 g_xn_hi[ROWS * DIM];
__device__ bf16 g_xn_lo[ROWS * DIM];
__device__ bf16 g_wqT_hi[NQKV * KD];
__device__ bf16 g_wqT_lo[NQKV * KD];
__device__ bf16 g_woT_hi[DIM * KD];
__device__ bf16 g_woT_lo[DIM * KD];
__device__ bf16 g_q_hi[BB*HH*NN*DH];
__device__ bf16 g_q_lo[BB*HH*NN*DH];
__device__ bf16 g_k_hi[BB*HH*NN*DH];
__device__ bf16 g_k_lo[BB*HH*NN*DH];
__device__ bf16 g_v_hi[BB*HH*NN*DH];
__device__ bf16 g_v_lo[BB*HH*NN*DH];
__device__ bf16 g_o_hi[ROWS * INNER];
__device__ bf16 g_o_lo[ROWS * INNER];

// ---------------------------------------------------------------------------
// Helpers
// ---------------------------------------------------------------------------
__device__ __forceinline__ uint32_t smem_u32(const void* p) {
    uint32_t a;
    asm("{ .reg .u64 t; cvta.to.shared.u64 t, %1; cvt.u32.u64 %0, t; }" : "=r"(a) : "l"(p));
    return a;
}
#define SWZ128(x) ((x) ^ (((x) >> 3) & 0x70))

__device__ __forceinline__ void cp16(uint32_t dst, const void* src) {
    size_t g = __cvta_generic_to_global(src);
    asm volatile("cp.async.cg.shared.global [%0], [%1], 16;" :: "r"(dst), "l"(g) : "memory");
}
__device__ __forceinline__ void cp_commit() { asm volatile("cp.async.commit_group;" ::: "memory"); }
__device__ __forceinline__ void cp_wait0()  { asm volatile("cp.async.wait_group 0;"  ::: "memory"); }
__device__ __forceinline__ void cp_wait1()  { asm volatile("cp.async.wait_group 1;"  ::: "memory"); }
__device__ __forceinline__ void cp_wait2()  { asm volatile("cp.async.wait_group 2;"  ::: "memory"); }

__device__ __forceinline__ void ldsm4(uint32_t* r, uint32_t a) {
    asm volatile("ldmatrix.sync.aligned.m8n8.x4.shared.b16 {%0,%1,%2,%3}, [%4];"
        : "=r"(r[0]),"=r"(r[1]),"=r"(r[2]),"=r"(r[3]) : "r"(a));
}
__device__ __forceinline__ void ldsm4t(uint32_t* r, uint32_t a) {
    asm volatile("ldmatrix.sync.aligned.m8n8.x4.trans.shared.b16 {%0,%1,%2,%3}, [%4];"
        : "=r"(r[0]),"=r"(r[1]),"=r"(r[2]),"=r"(r[3]) : "r"(a));
}
__device__ __forceinline__ void mma16816(float* c, const uint32_t* a, const uint32_t* b) {
    asm volatile("mma.sync.aligned.m16n8k16.row.col.f32.bf16.bf16.f32 "
        "{%0,%1,%2,%3}, {%4,%5,%6,%7}, {%8,%9}, {%0,%1,%2,%3};"
        : "+f"(c[0]),"+f"(c[1]),"+f"(c[2]),"+f"(c[3])
        : "r"(a[0]),"r"(a[1]),"r"(a[2]),"r"(a[3]), "r"(b[0]),"r"(b[1]));
}
__device__ __forceinline__ uint32_t pack2(float x, float y) {
    __nv_bfloat162 t = __floats2bfloat162_rn(x, y);
    return *(uint32_t*)&t;
}
__device__ __forceinline__ float bhi(float v) {
    return __bfloat162float(__float2bfloat16(v));
}
__device__ __forceinline__ void f2hl(float v, bf16& h, bf16& l) {
    h = __float2bfloat16(v);
    l = __float2bfloat16(v - __bfloat162float(h));
}
__device__ __forceinline__ float ex2f(float x) {
    float y; asm("ex2.approx.f32 %0, %1;" : "=f"(y) : "f"(x)); return y;
}

// ---------------------------------------------------------------------------
// LayerNorm -> bf16 hi/lo
// ---------------------------------------------------------------------------
__global__ void ln_split_kernel(const float* __restrict__ x,
                                const float* __restrict__ gamma,
                                const float* __restrict__ beta,
                                bf16* __restrict__ xh, bf16* __restrict__ xl) {
    const int row = blockIdx.x;
    const int t   = threadIdx.x;
    float4 v = ((const float4*)(x + (size_t)row * DIM))[t];
    float s  = v.x + v.y + v.z + v.w;
    float sq = v.x*v.x + v.y*v.y + v.z*v.z + v.w*v.w;
    #pragma unroll
    for (int o = 16; o > 0; o >>= 1) {
        s  += __shfl_down_sync(0xffffffffu, s,  o);
        sq += __shfl_down_sync(0xffffffffu, sq, o);
    }
    __shared__ float ws[8], wq[8], s_mu, s_rstd;
    const int lane = t & 31, wid = t >> 5;
    if (lane == 0) { ws[wid] = s; wq[wid] = sq; }
    __syncthreads();
    if (t == 0) {
        float S = 0.f, Q = 0.f;
        #pragma unroll
        for (int i = 0; i < 8; i++) { S += ws[i]; Q += wq[i]; }
        float mu = S * (1.0f / DIM);
        float var = Q * (1.0f / DIM) - mu * mu;
        s_mu = mu; s_rstd = rsqrtf(var + LN_EPS);
    }
    __syncthreads();
    const float mu = s_mu, rstd = s_rstd;
    float4 g = ((const float4*)gamma)[t];
    float4 b = ((const float4*)beta)[t];
    float y0 = (v.x-mu)*rstd*g.x + b.x, y1 = (v.y-mu)*rstd*g.y + b.y;
    float y2 = (v.z-mu)*rstd*g.z + b.z, y3 = (v.w-mu)*rstd*g.w + b.w;
    bf16 h0,h1,h2,h3,l0,l1,l2,l3;
    f2hl(y0,h0,l0); f2hl(y1,h1,l1); f2hl(y2,h2,l2); f2hl(y3,h3,l3);
    __nv_bfloat162* H = (__nv_bfloat162*)(xh + (size_t)row * DIM);
    __nv_bfloat162* L = (__nv_bfloat162*)(xl + (size_t)row * DIM);
    H[2*t]   = __halves2bfloat162(h0,h1);  H[2*t+1] = __halves2bfloat162(h2,h3);
    L[2*t]   = __halves2bfloat162(l0,l1);  L[2*t+1] = __halves2bfloat162(l2,l3);
}

// ---------------------------------------------------------------------------
// W[K][N] f32 -> WT hi/lo [N][K] bf16
// ---------------------------------------------------------------------------
__global__ void transpose_split_kernel(const float* __restrict__ W,
                                       bf16* __restrict__ Th, bf16* __restrict__ Tl,
                                       int Kd, int Nd) {
    __shared__ float t[32][33];
    const int n0 = blockIdx.x * 32, k0 = blockIdx.y * 32;
    const int tx = threadIdx.x, ty = threadIdx.y;
    #pragma unroll
    for (int i = 0; i < 32; i += 8)
        t[ty + i][tx] = W[(size_t)(k0 + ty + i) * Nd + n0 + tx];
    __syncthreads();
    #pragma unroll
    for (int i = 0; i < 32; i += 8) {
        float v = t[tx][ty + i];
        bf16 h, l; f2hl(v, h, l);
        const size_t idx = (size_t)(n0 + ty + i) * Kd + k0 + tx;
        Th[idx] = h; Tl[idx] = l;
    }
}

// ---------------------------------------------------------------------------
// mma.sync split-bf16 GEMM. BK=32 chunks stored as 128B rows [hi(64B)|lo(64B)]
// (SW128, conflict-free ldmatrix; lo frag = hi addr ^ 64). Stage = 32KB,
// 3 stages = 96KB -> 2 CTAs/SM AND depth-2 cp.async prefetch.
// Loader: 8 threads per 128B row; lanes 0-3 pull 64B contiguous from hi src,
// lanes 4-7 from lo src (full sector utilization — R10's loader scattered
// 16B requests across 2KB-strided rows, which was the regression).
// ---------------------------------------------------------------------------
#define GBK      32
#define GREG_B   16384             // one region (A or B): 128 rows x 128B
#define GSTAGE_B (2*GREG_B)        // 32KB: A then B
#define GSTAGES  3
#define GNC      (KD / GBK)        // 32 chunks
#define GEMM_SMEM (GSTAGES*GSTAGE_B)   // 98304

template<int EPI>
__global__ void __launch_bounds__(256, 2)
gemm_mma_kernel(const bf16* __restrict__ Ah, const bf16* __restrict__ Al,
                const bf16* __restrict__ Bh, const bf16* __restrict__ Bl,
                bf16* __restrict__ qh, bf16* __restrict__ ql,
                bf16* __restrict__ kh, bf16* __restrict__ kl,
                bf16* __restrict__ vh, bf16* __restrict__ vl,
                const float* __restrict__ bias, float* __restrict__ outf) {
    extern __shared__ char smem[];
    const uint32_t sb = smem_u32(smem);
    const int tid = threadIdx.x;
    const int w = tid >> 5, lane = tid & 31;
    const int wm = w >> 2, wn = w & 3;
    const int brow = blockIdx.y * 128;
    const int bcol = blockIdx.x * 128;

    // Loader geometry: row = tid>>3, lane-slot lc = tid&7.
    // lc 0-3 -> hi source bytes [0,64); lc 4-7 -> lo source bytes [64,128).
    const int lrow = tid >> 3, lc = tid & 7;
    const uint32_t ldst = SWZ128(lrow * 128 + lc * 16);
    const bf16* srcA = ((lc < 4) ? Ah : Al) + (size_t)(brow + lrow) * KD + (lc & 3) * 8;
    const bf16* srcB = ((lc < 4) ? Bh : Bl) + (size_t)(bcol + lrow) * KD + (lc & 3) * 8;

    auto load_chunk = [&](int stage, int ch) {
        const uint32_t bb = sb + stage * GSTAGE_B;
        const size_t ko = (size_t)ch * GBK;
        #pragma unroll
        for (int sub = 0; sub < 4; sub++) {
            const uint32_t d = ldst + sub * 4096;            // 32 rows * 128B
            const size_t go = ko + (size_t)sub * 32 * KD;
            cp16(bb + d,          srcA + go);
            cp16(bb + GREG_B + d, srcB + go);
        }
    };

    // Fragment bases (SW128 row-swizzle; col bits <128 are XOR-composable)
    const int grp = lane >> 3, r8 = lane & 7;
    uint32_t aSwz[4], bSwz[2];
    #pragma unroll
    for (int mf = 0; mf < 4; mf++) {
        const int arow = wm*64 + mf*16 + (lane & 15);
        aSwz[mf] = SWZ128(arow * 128) ^ ((lane >> 4) << 4);
    }
    #pragma unroll
    for (int bt = 0; bt < 2; bt++) {
        const int brw = wn*32 + bt*16 + r8 + ((grp & 2) ? 8 : 0);
        bSwz[bt] = SWZ128(brw * 128) ^ ((grp & 1) ? 16 : 0);
    }

    float acc[4][4][4] = {};

    load_chunk(0, 0); cp_commit();
    load_chunk(1, 1); cp_commit();

    for (int ch = 0; ch < GNC; ch++) {
        if (ch + 2 < GNC) load_chunk((ch + 2) % GSTAGES, ch + 2);
        cp_commit();          // empty groups retire immediately; keeps wait-count exact
        cp_wait2();           // all but the 2 newest groups complete -> chunk ch ready
        __syncthreads();
        const uint32_t bb = sb + (ch % GSTAGES) * GSTAGE_B;

        #pragma unroll
        for (int ks = 0; ks < 2; ks++) {
            uint32_t Bf[2][2][4];
            #pragma unroll
            for (int bt = 0; bt < 2; bt++) {
                const uint32_t bo = bSwz[bt] ^ (ks * 32);
                ldsm4(Bf[0][bt], bb + GREG_B + bo);
                ldsm4(Bf[1][bt], bb + GREG_B + (bo ^ 64));
            }
            #pragma unroll
            for (int mf = 0; mf < 4; mf++) {
                uint32_t Ah4[4], Al4[4];
                const uint32_t ao = aSwz[mf] ^ (ks * 32);
                ldsm4(Ah4, bb + ao);
                ldsm4(Al4, bb + (ao ^ 64));
                #pragma unroll
                for (int nf = 0; nf < 4; nf++) {
                    const uint32_t* bh2 = &Bf[0][nf >> 1][(nf & 1) * 2];
                    const uint32_t* bl2 = &Bf[1][nf >> 1][(nf & 1) * 2];
                    mma16816(acc[mf][nf], Ah4, bh2);
                    mma16816(acc[mf][nf], Ah4, bl2);
                    mma16816(acc[mf][nf], Al4, bh2);
                }
            }
        }
        __syncthreads();      // compute done before this stage is overwritten
    }

    const int t4 = lane >> 2, t2 = (lane & 3) * 2;
    if (EPI == 0) {
        const int part = bcol >> 10;
        bf16* dh = (part == 0) ? qh : (part == 1) ? kh : vh;
        bf16* dl = (part == 0) ? ql : (part == 1) ? kl : vl;
        #pragma unroll
        for (int mf = 0; mf < 4; mf++) {
            #pragma unroll
            for (int nf = 0; nf < 4; nf++) {
                const int c0 = bcol + wn*32 + nf*8 + t2;
                const int inner = c0 & 1023;
                const int hh_ = inner >> 6, d = inner & 63;
                #pragma unroll
                for (int rr = 0; rr < 2; rr++) {
                    const int m = brow + wm*64 + mf*16 + t4 + rr*8;
                    const int bq = m >> 11, n = m & 2047;
                    const size_t idx = (((size_t)(bq*HH + hh_))*NN + n)*DH + d;
                    float v0 = acc[mf][nf][rr*2], v1 = acc[mf][nf][rr*2+1];
                    *(uint32_t*)(dh + idx) = pack2(v0, v1);
                    *(uint32_t*)(dl + idx) = pack2(v0 - bhi(v0), v1 - bhi(v1));
                }
            }
        }
    } else {
        #pragma unroll
        for (int mf = 0; mf < 4; mf++) {
            #pragma unroll
            for (int nf = 0; nf < 4; nf++) {
                const int c0 = bcol + wn*32 + nf*8 + t2;
                #pragma unroll
                for (int rr = 0; rr < 2; rr++) {
                    const int m = brow + wm*64 + mf*16 + t4 + rr*8;
                    float2 o2;
                    o2.x = acc[mf][nf][rr*2]   + bias[c0];
                    o2.y = acc[mf][nf][rr*2+1] + bias[c0+1];
                    *(float2*)(outf + (size_t)m * DIM + c0) = o2;
                }
            }
        }
    }
}

// ---------------------------------------------------------------------------
// Attention: FA2-style mma.sync, split-bf16. Double-buffered KV (2x32KB)
// + Q_lo smem (16KB) = 80KB/CTA -> 2 CTAs/SM with depth-1 prefetch.
// ---------------------------------------------------------------------------
#define ATILE_B   8192
#define ASTAGE_B  (4*ATILE_B)        // 32KB: Kh,Kl,Vh,Vl
#define AQLO      (2*ASTAGE_B)       // 65536
#define ATTN_SMEM (AQLO + 16384)     // 81920

__global__ void __launch_bounds__(256, 2)
attn_mma_kernel(const bf16* __restrict__ Qh, const bf16* __restrict__ Ql,
                const bf16* __restrict__ Kh, const bf16* __restrict__ Kl,
                const bf16* __restrict__ Vh, const bf16* __restrict__ Vl,
                bf16* __restrict__ Ohi, bf16* __restrict__ Olo) {
    extern __shared__ char smem[];
    const uint32_t sb = smem_u32(smem);
    const int tid = threadIdx.x;
    const int w = tid >> 5, lane = tid & 31;
    const int grp = lane >> 3, r8 = lane & 7;
    const int qt = blockIdx.x, hh_ = blockIdx.y, bq = blockIdx.z;
    const size_t hb = ((size_t)(bq*HH + hh_)) * NN * DH;

    const int lrow = tid >> 3, lc = tid & 7;
    const uint32_t ldst = SWZ128(lrow * 128 + lc * 16);

    // ---- Stage Q: hi into stage-0 region (transient), lo into AQLO ----
    {
        const bf16* qsh = Qh + hb + (size_t)qt*128*DH + lc*8;
        const bf16* qsl = Ql + hb + (size_t)qt*128*DH + lc*8;
        #pragma unroll
        for (int s = 0; s < 4; s++) {
            const size_t go = (size_t)(lrow + s*32) * DH;
            cp16(sb + ldst + s*4096,        qsh + go);
            cp16(sb + AQLO + ldst + s*4096, qsl + go);
        }
        cp_commit(); cp_wait0();
    }
    __syncthreads();
    const int qrow = w*16 + (lane & 15);
    const uint32_t rb = SWZ128(qrow * 128) ^ ((lane >> 4) << 4);
    uint32_t qfh[4][4];
    #pragma unroll
    for (int ks = 0; ks < 4; ks++) ldsm4(qfh[ks], sb + (rb ^ (ks * 32)));
    __syncthreads();   // Q_hi extraction done; stage-0 may be overwritten

    // K fragment row bases
    uint32_t kSwz[4];
    #pragma unroll
    for (int p = 0; p < 4; p++) {
        const int brw = p*16 + r8 + ((grp & 2) ? 8 : 0);
        kSwz[p] = SWZ128(brw * 128) ^ ((grp & 1) ? 16 : 0);
    }
    const int vrsub = r8 + ((grp & 1) ? 8 : 0);
    const uint32_t vcoff = (grp & 2) ? 16 : 0;

    const bf16* kp0 = Kh + hb + (size_t)lrow * DH + lc*8;
    const bf16* kp1 = Kl + hb + (size_t)lrow * DH + lc*8;
    const bf16* kp2 = Vh + hb + (size_t)lrow * DH + lc*8;
    const bf16* kp3 = Vl + hb + (size_t)lrow * DH + lc*8;

    auto load_tile = [&](int stage, int t) {
        const uint32_t bb = sb + stage * ASTAGE_B;
        const size_t tb = (size_t)t * 64 * DH;
        #pragma unroll
        for (int sub = 0; sub < 2; sub++) {
            const uint32_t d = ldst + sub * 4096;
            const size_t go = tb + (size_t)sub * 32 * DH;
            cp16(bb + 0*ATILE_B + d, kp0 + go);
            cp16(bb + 1*ATILE_B + d, kp1 + go);
            cp16(bb + 2*ATILE_B + d, kp2 + go);
            cp16(bb + 3*ATILE_B + d, kp3 + go);
        }
    };

    float oacc[8][4] = {};
    float dsum0 = 0.f, dsum1 = 0.f;

    load_tile(0, 0); cp_commit();

    for (int t = 0; t < NN/64; t++) {
        if (t + 1 < NN/64) load_tile((t + 1) & 1, t + 1);
        cp_commit();
        cp_wait1();
        __syncthreads();
        const uint32_t bb = sb + (t & 1) * ASTAGE_B;

        // ---- S = Q K^T ----
        float sacc[8][4] = {};
        #pragma unroll
        for (int ks = 0; ks < 4; ks++) {
            uint32_t qfl[4];
            ldsm4(qfl, sb + AQLO + (rb ^ (ks * 32)));
            #pragma unroll
            for (int p = 0; p < 4; p++) {
                uint32_t Kh4[4], Kl4[4];
                const uint32_t ad = bb + (kSwz[p] ^ (ks * 32));
                ldsm4(Kh4, ad);
                ldsm4(Kl4, ad + ATILE_B);
                #pragma unroll
                for (int q = 0; q < 2; q++) {
                    mma16816(sacc[2*p+q], qfh[ks], &Kh4[q*2]);
                    mma16816(sacc[2*p+q], qfh[ks], &Kl4[q*2]);
                    mma16816(sacc[2*p+q], qfl,     &Kh4[q*2]);
                }
            }
        }

        // ---- O += exp(S) V ----
        #pragma unroll
        for (int j = 0; j < 4; j++) {
            float pA[4], pB[4];
            #pragma unroll
            for (int e = 0; e < 4; e++) pA[e] = ex2f(sacc[2*j][e]   * SCL2E);
            #pragma unroll
            for (int e = 0; e < 4; e++) pB[e] = ex2f(sacc[2*j+1][e] * SCL2E);
            dsum0 += pA[0] + pA[1] + pB[0] + pB[1];
            dsum1 += pA[2] + pA[3] + pB[2] + pB[3];
            uint32_t pfh[4], pfl[4];
            pfh[0] = pack2(pA[0], pA[1]);  pfh[1] = pack2(pA[2], pA[3]);
            pfh[2] = pack2(pB[0], pB[1]);  pfh[3] = pack2(pB[2], pB[3]);
            pfl[0] = pack2(pA[0]-bhi(pA[0]), pA[1]-bhi(pA[1]));
            pfl[1] = pack2(pA[2]-bhi(pA[2]), pA[3]-bhi(pA[3]));
            pfl[2] = pack2(pB[0]-bhi(pB[0]), pB[1]-bhi(pB[1]));
            pfl[3] = pack2(pB[2]-bhi(pB[2]), pB[3]-bhi(pB[3]));
            const int vrow = j*16 + vrsub;
            const uint32_t vb = SWZ128(vrow * 128) ^ vcoff;
            #pragma unroll
            for (int p = 0; p < 4; p++) {
                uint32_t Vh4[4], Vl4[4];
                const uint32_t ad = bb + 2*ATILE_B + (vb ^ (p * 32));
                ldsm4t(Vh4, ad);
                ldsm4t(Vl4, ad + ATILE_B);
                #pragma unroll
                for (int q = 0; q < 2; q++) {
                    mma16816(oacc[2*p+q], pfh, &Vh4[q*2]);
                    mma16816(oacc[2*p+q], pfh, &Vl4[q*2]);
                    mma16816(oacc[2*p+q], pfl, &Vh4[q*2]);
                }
            }
        }
        __syncthreads();   // compute done before this stage is overwritten
    }

    // ---- normalize + store hi/lo bf16 [b, n, h*64+d] ----
    dsum0 += __shfl_xor_sync(0xffffffffu, dsum0, 1);
    dsum0 += __shfl_xor_sync(0xffffffffu, dsum0, 2);
    dsum1 += __shfl_xor_sync(0xffffffffu, dsum1, 1);
    dsum1 += __shfl_xor_sync(0xffffffffu, dsum1, 2);
    const float inv0 = 1.0f / (dsum0 + ATTN_EPS);
    const float inv1 = 1.0f / (dsum1 + ATTN_EPS);

    const int t4 = lane >> 2, t2 = (lane & 3) * 2;
    #pragma unroll
    for (int nf = 0; nf < 8; nf++) {
        const int d = nf*8 + t2;
        const int n0 = qt*128 + w*16 + t4;
        float v00 = oacc[nf][0]*inv0, v01 = oacc[nf][1]*inv0;
        float v10 = oacc[nf][2]*inv1, v11 = oacc[nf][3]*inv1;
        const size_t i0 = ((size_t)(bq*NN + n0)    )*INNER + hh_*DH + d;
        const size_t i1 = ((size_t)(bq*NN + n0 + 8))*INNER + hh_*DH + d;
        *(uint32_t*)(Ohi + i0) = pack2(v00, v01);
        *(uint32_t*)(Olo + i0) = pack2(v00 - bhi(v00), v01 - bhi(v01));
        *(uint32_t*)(Ohi + i1) = pack2(v10, v11);
        *(uint32_t*)(Olo + i1) = pack2(v10 - bhi(v10), v11 - bhi(v11));
    }
}

// ---------------------------------------------------------------------------
extern "C" void kernel_launch(void* const* d_in, const int* in_sizes, int n_in,
                              void* d_out, int out_size) {
    const float* x      = (const float*)d_in[0];
    const float* gamma  = (const float*)d_in[1];
    const float* beta   = (const float*)d_in[2];
    const float* w_qkv  = (const float*)d_in[3];
    const float* w_out  = (const float*)d_in[4];
    const float* b_out  = (const float*)d_in[5];
    float* out = (float*)d_out;

    bf16 *xh,*xl,*wqh,*wql,*woh,*wol,*qh,*ql,*kh,*kl,*vh,*vl,*oh,*ol;
    cudaGetSymbolAddress((void**)&xh,  g_xn_hi);
    cudaGetSymbolAddress((void**)&xl,  g_xn_lo);
    cudaGetSymbolAddress((void**)&wqh, g_wqT_hi);
    cudaGetSymbolAddress((void**)&wql, g_wqT_lo);
    cudaGetSymbolAddress((void**)&woh, g_woT_hi);
    cudaGetSymbolAddress((void**)&wol, g_woT_lo);
    cudaGetSymbolAddress((void**)&qh,  g_q_hi);
    cudaGetSymbolAddress((void**)&ql,  g_q_lo);
    cudaGetSymbolAddress((void**)&kh,  g_k_hi);
    cudaGetSymbolAddress((void**)&kl,  g_k_lo);
    cudaGetSymbolAddress((void**)&vh,  g_v_hi);
    cudaGetSymbolAddress((void**)&vl,  g_v_lo);
    cudaGetSymbolAddress((void**)&oh,  g_o_hi);
    cudaGetSymbolAddress((void**)&ol,  g_o_lo);

    cudaFuncSetAttribute(gemm_mma_kernel<0>, cudaFuncAttributeMaxDynamicSharedMemorySize, GEMM_SMEM);
    cudaFuncSetAttribute(gemm_mma_kernel<1>, cudaFuncAttributeMaxDynamicSharedMemorySize, GEMM_SMEM);
    cudaFuncSetAttribute(attn_mma_kernel,    cudaFuncAttributeMaxDynamicSharedMemorySize, ATTN_SMEM);

    ln_split_kernel<<<ROWS, 256>>>(x, gamma, beta, xh, xl);
    transpose_split_kernel<<<dim3(NQKV/32, KD/32), dim3(32, 8)>>>(w_qkv, wqh, wql, KD, NQKV);
    transpose_split_kernel<<<dim3(DIM/32,  KD/32), dim3(32, 8)>>>(w_out, woh, wol, KD, DIM);
    gemm_mma_kernel<0><<<dim3(NQKV/128, ROWS/128), 256, GEMM_SMEM>>>(
        xh, xl, wqh, wql, qh, ql, kh, kl, vh, vl, nullptr, nullptr);
    attn_mma_kernel<<<dim3(NN/128, HH, BB), 256, ATTN_SMEM>>>(
        qh, ql, kh, kl, vh, vl, oh, ol);
    gemm_mma_kernel<1><<<dim3(DIM/128, ROWS/128), 256, GEMM_SMEM>>>(
        oh, ol, woh, wol, nullptr, nullptr, nullptr, nullptr, nullptr, nullptr, b_out, out);
}

// round 12
// speedup vs baseline: 1.5872x; 1.5872x over previous
#include <cuda_runtime.h>
#include <cuda_bf16.h>
#include <cuda_fp16.h>
#include <math.h>
#include <stdint.h>

typedef __nv_bfloat16 bf16;

#define BB     2
#define NN     2048
#define DIM    1024
#define HH     16
#define DH     64
#define INNER  1024
#define ROWS   (BB*NN)       // 4096
#define NQKV   3072
#define KD     1024
#define LN_EPS   1e-5f
#define ATTN_EPS 1e-8f
#define SCALE    0.125f
#define SCL2E    0.1803368801111244f   // SCALE * log2(e)

// ---------------------------------------------------------------------------
// Scratch (device globals)
// ---------------------------------------------------------------------------
__device__ bf16 g_xn_hi[ROWS * DIM];
__device__ bf16 g_xn_lo[ROWS * DIM];
__device__ bf16 g_wqT_hi[NQKV * KD];
__device__ bf16 g_wqT_lo[NQKV * KD];
__device__ bf16 g_woT_hi[DIM * KD];
__device__ bf16 g_woT_lo[DIM * KD];
__device__ __half g_q[BB*HH*NN*DH];
__device__ __half g_k[BB*HH*NN*DH];
__device__ __half g_v[BB*HH*NN*DH];
__device__ bf16 g_o_hi[ROWS * INNER];
__device__ bf16 g_o_lo[ROWS * INNER];

// ---------------------------------------------------------------------------
// Helpers
// ---------------------------------------------------------------------------
__device__ __forceinline__ uint32_t smem_u32(const void* p) {
    uint32_t a;
    asm("{ .reg .u64 t; cvta.to.shared.u64 t, %1; cvt.u32.u64 %0, t; }" : "=r"(a) : "l"(p));
    return a;
}
#define SWZ128(x) ((x) ^ (((x) >> 3) & 0x70))

__device__ __forceinline__ void cp16(uint32_t dst, const void* src) {
    size_t g = __cvta_generic_to_global(src);
    asm volatile("cp.async.cg.shared.global [%0], [%1], 16;" :: "r"(dst), "l"(g) : "memory");
}
__device__ __forceinline__ void cp_commit() { asm volatile("cp.async.commit_group;" ::: "memory"); }
__device__ __forceinline__ void cp_wait0()  { asm volatile("cp.async.wait_group 0;"  ::: "memory"); }
__device__ __forceinline__ void cp_wait1()  { asm volatile("cp.async.wait_group 1;"  ::: "memory"); }

__device__ __forceinline__ void ldsm4(uint32_t* r, uint32_t a) {
    asm volatile("ldmatrix.sync.aligned.m8n8.x4.shared.b16 {%0,%1,%2,%3}, [%4];"
        : "=r"(r[0]),"=r"(r[1]),"=r"(r[2]),"=r"(r[3]) : "r"(a));
}
__device__ __forceinline__ void ldsm4t(uint32_t* r, uint32_t a) {
    asm volatile("ldmatrix.sync.aligned.m8n8.x4.trans.shared.b16 {%0,%1,%2,%3}, [%4];"
        : "=r"(r[0]),"=r"(r[1]),"=r"(r[2]),"=r"(r[3]) : "r"(a));
}
// bf16 MMA (GEMMs)
__device__ __forceinline__ void mma16816(float* c, const uint32_t* a, const uint32_t* b) {
    asm volatile("mma.sync.aligned.m16n8k16.row.col.f32.bf16.bf16.f32 "
        "{%0,%1,%2,%3}, {%4,%5,%6,%7}, {%8,%9}, {%0,%1,%2,%3};"
        : "+f"(c[0]),"+f"(c[1]),"+f"(c[2]),"+f"(c[3])
        : "r"(a[0]),"r"(a[1]),"r"(a[2]),"r"(a[3]), "r"(b[0]),"r"(b[1]));
}
// fp16 MMA (attention)
__device__ __forceinline__ void mma16816h(float* c, const uint32_t* a, const uint32_t* b) {
    asm volatile("mma.sync.aligned.m16n8k16.row.col.f32.f16.f16.f32 "
        "{%0,%1,%2,%3}, {%4,%5,%6,%7}, {%8,%9}, {%0,%1,%2,%3};"
        : "+f"(c[0]),"+f"(c[1]),"+f"(c[2]),"+f"(c[3])
        : "r"(a[0]),"r"(a[1]),"r"(a[2]),"r"(a[3]), "r"(b[0]),"r"(b[1]));
}
__device__ __forceinline__ uint32_t pack2(float x, float y) {
    __nv_bfloat162 t = __floats2bfloat162_rn(x, y);
    return *(uint32_t*)&t;
}
__device__ __forceinline__ uint32_t pack2h(float x, float y) {
    __half2 t = __floats2half2_rn(x, y);
    return *(uint32_t*)&t;
}
__device__ __forceinline__ float bhi(float v) {
    return __bfloat162float(__float2bfloat16(v));
}
__device__ __forceinline__ void f2hl(float v, bf16& h, bf16& l) {
    h = __float2bfloat16(v);
    l = __float2bfloat16(v - __bfloat162float(h));
}
__device__ __forceinline__ float ex2f(float x) {
    float y; asm("ex2.approx.f32 %0, %1;" : "=f"(y) : "f"(x)); return y;
}

// ---------------------------------------------------------------------------
// LayerNorm -> bf16 hi/lo
// ---------------------------------------------------------------------------
__global__ void ln_split_kernel(const float* __restrict__ x,
                                const float* __restrict__ gamma,
                                const float* __restrict__ beta,
                                bf16* __restrict__ xh, bf16* __restrict__ xl) {
    const int row = blockIdx.x;
    const int t   = threadIdx.x;
    float4 v = ((const float4*)(x + (size_t)row * DIM))[t];
    float s  = v.x + v.y + v.z + v.w;
    float sq = v.x*v.x + v.y*v.y + v.z*v.z + v.w*v.w;
    #pragma unroll
    for (int o = 16; o > 0; o >>= 1) {
        s  += __shfl_down_sync(0xffffffffu, s,  o);
        sq += __shfl_down_sync(0xffffffffu, sq, o);
    }
    __shared__ float ws[8], wq[8], s_mu, s_rstd;
    const int lane = t & 31, wid = t >> 5;
    if (lane == 0) { ws[wid] = s; wq[wid] = sq; }
    __syncthreads();
    if (t == 0) {
        float S = 0.f, Q = 0.f;
        #pragma unroll
        for (int i = 0; i < 8; i++) { S += ws[i]; Q += wq[i]; }
        float mu = S * (1.0f / DIM);
        float var = Q * (1.0f / DIM) - mu * mu;
        s_mu = mu; s_rstd = rsqrtf(var + LN_EPS);
    }
    __syncthreads();
    const float mu = s_mu, rstd = s_rstd;
    float4 g = ((const float4*)gamma)[t];
    float4 b = ((const float4*)beta)[t];
    float y0 = (v.x-mu)*rstd*g.x + b.x, y1 = (v.y-mu)*rstd*g.y + b.y;
    float y2 = (v.z-mu)*rstd*g.z + b.z, y3 = (v.w-mu)*rstd*g.w + b.w;
    bf16 h0,h1,h2,h3,l0,l1,l2,l3;
    f2hl(y0,h0,l0); f2hl(y1,h1,l1); f2hl(y2,h2,l2); f2hl(y3,h3,l3);
    __nv_bfloat162* H = (__nv_bfloat162*)(xh + (size_t)row * DIM);
    __nv_bfloat162* L = (__nv_bfloat162*)(xl + (size_t)row * DIM);
    H[2*t]   = __halves2bfloat162(h0,h1);  H[2*t+1] = __halves2bfloat162(h2,h3);
    L[2*t]   = __halves2bfloat162(l0,l1);  L[2*t+1] = __halves2bfloat162(l2,l3);
}

// ---------------------------------------------------------------------------
// W[K][N] f32 -> WT hi/lo [N][K] bf16
// ---------------------------------------------------------------------------
__global__ void transpose_split_kernel(const float* __restrict__ W,
                                       bf16* __restrict__ Th, bf16* __restrict__ Tl,
                                       int Kd, int Nd) {
    __shared__ float t[32][33];
    const int n0 = blockIdx.x * 32, k0 = blockIdx.y * 32;
    const int tx = threadIdx.x, ty = threadIdx.y;
    #pragma unroll
    for (int i = 0; i < 32; i += 8)
        t[ty + i][tx] = W[(size_t)(k0 + ty + i) * Nd + n0 + tx];
    __syncthreads();
    #pragma unroll
    for (int i = 0; i < 32; i += 8) {
        float v = t[tx][ty + i];
        bf16 h, l; f2hl(v, h, l);
        const size_t idx = (size_t)(n0 + ty + i) * Kd + k0 + tx;
        Th[idx] = h; Tl[idx] = l;
    }
}

// ---------------------------------------------------------------------------
// mma.sync split-bf16 GEMM — EXACT R8 structure (best known: 193us, 65% tensor).
// Single-buffered 64KB smem stage -> 2 CTAs/SM, BK=64.
// EPI 0: write Q/K/V as SINGLE fp16 in [b,h,n,d]. EPI 1: +bias, f32 out.
// ---------------------------------------------------------------------------
#define GBK      64
#define GTILE_B  16384
#define GEMM_SMEM (4*GTILE_B)   // 65536 single stage: Ah,Al,Bh,Bl

template<int EPI>
__global__ void __launch_bounds__(256, 2)
gemm_mma_kernel(const bf16* __restrict__ Ah, const bf16* __restrict__ Al,
                const bf16* __restrict__ Bh, const bf16* __restrict__ Bl,
                __half* __restrict__ qh, __half* __restrict__ kh, __half* __restrict__ vh,
                const float* __restrict__ bias, float* __restrict__ outf) {
    extern __shared__ char smem[];
    const uint32_t sb = smem_u32(smem);
    const int tid = threadIdx.x;
    const int w = tid >> 5, lane = tid & 31;
    const int wm = w >> 2, wn = w & 3;
    const int brow = blockIdx.y * 128;
    const int bcol = blockIdx.x * 128;

    const int lrow = tid >> 3, lc = tid & 7;
    const uint32_t ldst = SWZ128(lrow * 128 + lc * 16);
    const bf16* gp0 = Ah + (size_t)(brow + lrow) * KD + lc * 8;
    const bf16* gp1 = Al + (size_t)(brow + lrow) * KD + lc * 8;
    const bf16* gp2 = Bh + (size_t)(bcol + lrow) * KD + lc * 8;
    const bf16* gp3 = Bl + (size_t)(bcol + lrow) * KD + lc * 8;

    const int grp = lane >> 3, r8 = lane & 7;
    uint32_t aSwz[4], bSwz[2];
    #pragma unroll
    for (int mf = 0; mf < 4; mf++) {
        const int arow = wm*64 + mf*16 + (lane & 15);
        aSwz[mf] = SWZ128(arow * 128) ^ ((lane >> 4) << 4);
    }
    #pragma unroll
    for (int bt = 0; bt < 2; bt++) {
        const int brw = wn*32 + bt*16 + r8 + ((grp & 2) ? 8 : 0);
        bSwz[bt] = SWZ128(brw * 128) ^ ((grp & 1) ? 16 : 0);
    }

    float acc[4][4][4] = {};

    for (int ch = 0; ch < KD / GBK; ch++) {
        __syncthreads();   // previous compute done before overwrite
        const size_t ko = (size_t)ch * GBK;
        #pragma unroll
        for (int sub = 0; sub < 4; sub++) {
            const uint32_t d = ldst + sub * 4096;
            const size_t go = (size_t)sub * 32 * KD + ko;
            cp16(sb + 0*GTILE_B + d, gp0 + go);
            cp16(sb + 1*GTILE_B + d, gp1 + go);
            cp16(sb + 2*GTILE_B + d, gp2 + go);
            cp16(sb + 3*GTILE_B + d, gp3 + go);
        }
        cp_commit(); cp_wait0();
        __syncthreads();   // publish

        #pragma unroll
        for (int ks = 0; ks < 4; ks++) {
            uint32_t Bf[2][2][4];
            #pragma unroll
            for (int bt = 0; bt < 2; bt++) {
                const uint32_t bd = sb + 2*GTILE_B + (bSwz[bt] ^ (ks * 32));
                ldsm4(Bf[0][bt], bd);
                ldsm4(Bf[1][bt], bd + GTILE_B);
            }
            #pragma unroll
            for (int mf = 0; mf < 4; mf++) {
                uint32_t Ah4[4], Al4[4];
                const uint32_t ad = sb + (aSwz[mf] ^ (ks * 32));
                ldsm4(Ah4, ad);
                ldsm4(Al4, ad + GTILE_B);
                #pragma unroll
                for (int nf = 0; nf < 4; nf++) {
                    const uint32_t* bh2 = &Bf[0][nf >> 1][(nf & 1) * 2];
                    const uint32_t* bl2 = &Bf[1][nf >> 1][(nf & 1) * 2];
                    mma16816(acc[mf][nf], Ah4, bh2);
                    mma16816(acc[mf][nf], Ah4, bl2);
                    mma16816(acc[mf][nf], Al4, bh2);
                }
            }
        }
    }

    const int t4 = lane >> 2, t2 = (lane & 3) * 2;
    if (EPI == 0) {
        const int part = bcol >> 10;
        __half* dst = (part == 0) ? qh : (part == 1) ? kh : vh;
        #pragma unroll
        for (int mf = 0; mf < 4; mf++) {
            #pragma unroll
            for (int nf = 0; nf < 4; nf++) {
                const int c0 = bcol + wn*32 + nf*8 + t2;
                const int inner = c0 & 1023;
                const int hh_ = inner >> 6, d = inner & 63;
                #pragma unroll
                for (int rr = 0; rr < 2; rr++) {
                    const int m = brow + wm*64 + mf*16 + t4 + rr*8;
                    const int bq = m >> 11, n = m & 2047;
                    const size_t idx = (((size_t)(bq*HH + hh_))*NN + n)*DH + d;
                    *(uint32_t*)(dst + idx) = pack2h(acc[mf][nf][rr*2], acc[mf][nf][rr*2+1]);
                }
            }
        }
    } else {
        #pragma unroll
        for (int mf = 0; mf < 4; mf++) {
            #pragma unroll
            for (int nf = 0; nf < 4; nf++) {
                const int c0 = bcol + wn*32 + nf*8 + t2;
                #pragma unroll
                for (int rr = 0; rr < 2; rr++) {
                    const int m = brow + wm*64 + mf*16 + t4 + rr*8;
                    float2 o2;
                    o2.x = acc[mf][nf][rr*2]   + bias[c0];
                    o2.y = acc[mf][nf][rr*2+1] + bias[c0+1];
                    *(float2*)(outf + (size_t)m * DIM + c0) = o2;
                }
            }
        }
    }
}

// ---------------------------------------------------------------------------
// Attention: FA2-style, SINGLE-precision fp16 MMAs (3x fewer than split-bf16;
// fp16's 11-bit mantissa keeps exp-arg error ~4e-4, well under tolerance).
// KV stage 16KB, double-buffered = 32KB total; Q fully register-resident.
// ---------------------------------------------------------------------------
#define ATILE_B   8192               // K or V: 64 rows x 128B
#define ASTAGE_B  (2*ATILE_B)        // 16KB: K,V
#define ATTN_SMEM (2*ASTAGE_B)       // 32768

__global__ void __launch_bounds__(256, 2)
attn_mma_kernel(const __half* __restrict__ Q, const __half* __restrict__ K,
                const __half* __restrict__ V,
                bf16* __restrict__ Ohi, bf16* __restrict__ Olo) {
    extern __shared__ char smem[];
    const uint32_t sb = smem_u32(smem);
    const int tid = threadIdx.x;
    const int w = tid >> 5, lane = tid & 31;
    const int grp = lane >> 3, r8 = lane & 7;
    const int qt = blockIdx.x, hh_ = blockIdx.y, bq = blockIdx.z;
    const size_t hb = ((size_t)(bq*HH + hh_)) * NN * DH;

    const int lrow = tid >> 3, lc = tid & 7;
    const uint32_t ldst = SWZ128(lrow * 128 + lc * 16);

    // ---- Stage Q tile (128 x 64 fp16 = 16KB) transiently in stage 0 ----
    {
        const __half* qs = Q + hb + (size_t)qt*128*DH + lc*8;
        #pragma unroll
        for (int s = 0; s < 4; s++)
            cp16(sb + ldst + s*4096, qs + (size_t)(lrow + s*32) * DH);
        cp_commit(); cp_wait0();
    }
    __syncthreads();
    const int qrow = w*16 + (lane & 15);
    const uint32_t rb = SWZ128(qrow * 128) ^ ((lane >> 4) << 4);
    uint32_t qf[4][4];
    #pragma unroll
    for (int ks = 0; ks < 4; ks++) ldsm4(qf[ks], sb + (rb ^ (ks * 32)));
    __syncthreads();   // Q extracted; stage 0 may be overwritten

    // Fragment row bases
    uint32_t kSwz[4];
    #pragma unroll
    for (int p = 0; p < 4; p++) {
        const int brw = p*16 + r8 + ((grp & 2) ? 8 : 0);
        kSwz[p] = SWZ128(brw * 128) ^ ((grp & 1) ? 16 : 0);
    }
    const int vrsub = r8 + ((grp & 1) ? 8 : 0);
    const uint32_t vcoff = (grp & 2) ? 16 : 0;

    const __half* kp = K + hb + (size_t)lrow * DH + lc*8;
    const __half* vp = V + hb + (size_t)lrow * DH + lc*8;

    auto load_tile = [&](int stage, int t) {
        const uint32_t bb = sb + stage * ASTAGE_B;
        const size_t tb = (size_t)t * 64 * DH;
        #pragma unroll
        for (int sub = 0; sub < 2; sub++) {
            const uint32_t d = ldst + sub * 4096;
            const size_t go = tb + (size_t)sub * 32 * DH;
            cp16(bb + d,           kp + go);
            cp16(bb + ATILE_B + d, vp + go);
        }
    };

    float oacc[8][4] = {};
    float dsum0 = 0.f, dsum1 = 0.f;

    load_tile(0, 0); cp_commit();

    for (int t = 0; t < NN/64; t++) {
        if (t + 1 < NN/64) load_tile((t + 1) & 1, t + 1);
        cp_commit();
        cp_wait1();
        __syncthreads();
        const uint32_t bb = sb + (t & 1) * ASTAGE_B;

        // ---- S = Q K^T (fp16 single) ----
        float sacc[8][4] = {};
        #pragma unroll
        for (int ks = 0; ks < 4; ks++) {
            #pragma unroll
            for (int p = 0; p < 4; p++) {
                uint32_t Kf[4];
                ldsm4(Kf, bb + (kSwz[p] ^ (ks * 32)));
                mma16816h(sacc[2*p+0], qf[ks], &Kf[0]);
                mma16816h(sacc[2*p+1], qf[ks], &Kf[2]);
            }
        }

        // ---- O += exp(S) V (fp16 single) ----
        #pragma unroll
        for (int j = 0; j < 4; j++) {
            float pA[4], pB[4];
            #pragma unroll
            for (int e = 0; e < 4; e++) pA[e] = ex2f(sacc[2*j][e]   * SCL2E);
            #pragma unroll
            for (int e = 0; e < 4; e++) pB[e] = ex2f(sacc[2*j+1][e] * SCL2E);
            dsum0 += pA[0] + pA[1] + pB[0] + pB[1];
            dsum1 += pA[2] + pA[3] + pB[2] + pB[3];
            uint32_t pf[4];
            pf[0] = pack2h(pA[0], pA[1]);  pf[1] = pack2h(pA[2], pA[3]);
            pf[2] = pack2h(pB[0], pB[1]);  pf[3] = pack2h(pB[2], pB[3]);
            const int vrow = j*16 + vrsub;
            const uint32_t vb = SWZ128(vrow * 128) ^ vcoff;
            #pragma unroll
            for (int p = 0; p < 4; p++) {
                uint32_t Vf[4];
                ldsm4t(Vf, bb + ATILE_B + (vb ^ (p * 32)));
                mma16816h(oacc[2*p+0], pf, &Vf[0]);
                mma16816h(oacc[2*p+1], pf, &Vf[2]);
            }
        }
        __syncthreads();   // compute done before this stage is overwritten
    }

    // ---- normalize + store hi/lo bf16 [b, n, h*64+d] ----
    dsum0 += __shfl_xor_sync(0xffffffffu, dsum0, 1);
    dsum0 += __shfl_xor_sync(0xffffffffu, dsum0, 2);
    dsum1 += __shfl_xor_sync(0xffffffffu, dsum1, 1);
    dsum1 += __shfl_xor_sync(0xffffffffu, dsum1, 2);
    const float inv0 = 1.0f / (dsum0 + ATTN_EPS);
    const float inv1 = 1.0f / (dsum1 + ATTN_EPS);

    const int t4 = lane >> 2, t2 = (lane & 3) * 2;
    #pragma unroll
    for (int nf = 0; nf < 8; nf++) {
        const int d = nf*8 + t2;
        const int n0 = qt*128 + w*16 + t4;
        float v00 = oacc[nf][0]*inv0, v01 = oacc[nf][1]*inv0;
        float v10 = oacc[nf][2]*inv1, v11 = oacc[nf][3]*inv1;
        const size_t i0 = ((size_t)(bq*NN + n0)    )*INNER + hh_*DH + d;
        const size_t i1 = ((size_t)(bq*NN + n0 + 8))*INNER + hh_*DH + d;
        *(uint32_t*)(Ohi + i0) = pack2(v00, v01);
        *(uint32_t*)(Olo + i0) = pack2(v00 - bhi(v00), v01 - bhi(v01));
        *(uint32_t*)(Ohi + i1) = pack2(v10, v11);
        *(uint32_t*)(Olo + i1) = pack2(v10 - bhi(v10), v11 - bhi(v11));
    }
}

// ---------------------------------------------------------------------------
extern "C" void kernel_launch(void* const* d_in, const int* in_sizes, int n_in,
                              void* d_out, int out_size) {
    const float* x      = (const float*)d_in[0];
    const float* gamma  = (const float*)d_in[1];
    const float* beta   = (const float*)d_in[2];
    const float* w_qkv  = (const float*)d_in[3];
    const float* w_out  = (const float*)d_in[4];
    const float* b_out  = (const float*)d_in[5];
    float* out = (float*)d_out;

    bf16 *xh,*xl,*wqh,*wql,*woh,*wol,*oh,*ol;
    __half *q,*k,*v;
    cudaGetSymbolAddress((void**)&xh,  g_xn_hi);
    cudaGetSymbolAddress((void**)&xl,  g_xn_lo);
    cudaGetSymbolAddress((void**)&wqh, g_wqT_hi);
    cudaGetSymbolAddress((void**)&wql, g_wqT_lo);
    cudaGetSymbolAddress((void**)&woh, g_woT_hi);
    cudaGetSymbolAddress((void**)&wol, g_woT_lo);
    cudaGetSymbolAddress((void**)&q,   g_q);
    cudaGetSymbolAddress((void**)&k,   g_k);
    cudaGetSymbolAddress((void**)&v,   g_v);
    cudaGetSymbolAddress((void**)&oh,  g_o_hi);
    cudaGetSymbolAddress((void**)&ol,  g_o_lo);

    cudaFuncSetAttribute(gemm_mma_kernel<0>, cudaFuncAttributeMaxDynamicSharedMemorySize, GEMM_SMEM);
    cudaFuncSetAttribute(gemm_mma_kernel<1>, cudaFuncAttributeMaxDynamicSharedMemorySize, GEMM_SMEM);
    cudaFuncSetAttribute(attn_mma_kernel,    cudaFuncAttributeMaxDynamicSharedMemorySize, ATTN_SMEM);

    ln_split_kernel<<<ROWS, 256>>>(x, gamma, beta, xh, xl);
    transpose_split_kernel<<<dim3(NQKV/32, KD/32), dim3(32, 8)>>>(w_qkv, wqh, wql, KD, NQKV);
    transpose_split_kernel<<<dim3(DIM/32,  KD/32), dim3(32, 8)>>>(w_out, woh, wol, KD, DIM);
    gemm_mma_kernel<0><<<dim3(NQKV/128, ROWS/128), 256, GEMM_SMEM>>>(
        xh, xl, wqh, wql, q, k, v, nullptr, nullptr);
    attn_mma_kernel<<<dim3(NN/128, HH, BB), 256, ATTN_SMEM>>>(q, k, v, oh, ol);
    gemm_mma_kernel<1><<<dim3(DIM/128, ROWS/128), 256, GEMM_SMEM>>>(
        oh, ol, woh, wol, nullptr, nullptr, nullptr, b_out, out);
}

// round 13
// speedup vs baseline: 3.1118x; 1.9605x over previous
#include <cuda_runtime.h>
#include <cuda_bf16.h>
#include <cuda_fp16.h>
#include <math.h>
#include <stdint.h>

#define BB     2
#define NN     2048
#define DIM    1024
#define HH     16
#define DH     64
#define INNER  1024
#define ROWS   (BB*NN)       // 4096
#define NQKV   3072
#define KD     1024
#define LN_EPS   1e-5f
#define ATTN_EPS 1e-8f
#define SCALE    0.125f
#define SCL2E    0.1803368801111244f   // SCALE * log2(e)

// ---------------------------------------------------------------------------
// Scratch (device globals) — all GEMM operands fp16 now
// ---------------------------------------------------------------------------
__device__ __half g_xn_hi[ROWS * DIM];
__device__ __half g_xn_lo[ROWS * DIM];
__device__ __half g_wqT[NQKV * KD];     // single fp16 weights (B side)
__device__ __half g_woT[DIM * KD];
__device__ __half g_q[BB*HH*NN*DH];
__device__ __half g_k[BB*HH*NN*DH];
__device__ __half g_v[BB*HH*NN*DH];
__device__ __half g_o_hi[ROWS * INNER];
__device__ __half g_o_lo[ROWS * INNER];

// ---------------------------------------------------------------------------
// Helpers
// ---------------------------------------------------------------------------
__device__ __forceinline__ uint32_t smem_u32(const void* p) {
    uint32_t a;
    asm("{ .reg .u64 t; cvta.to.shared.u64 t, %1; cvt.u32.u64 %0, t; }" : "=r"(a) : "l"(p));
    return a;
}
#define SWZ128(x) ((x) ^ (((x) >> 3) & 0x70))

__device__ __forceinline__ void cp16(uint32_t dst, const void* src) {
    size_t g = __cvta_generic_to_global(src);
    asm volatile("cp.async.cg.shared.global [%0], [%1], 16;" :: "r"(dst), "l"(g) : "memory");
}
__device__ __forceinline__ void cp_commit() { asm volatile("cp.async.commit_group;" ::: "memory"); }
__device__ __forceinline__ void cp_wait0()  { asm volatile("cp.async.wait_group 0;"  ::: "memory"); }
__device__ __forceinline__ void cp_wait1()  { asm volatile("cp.async.wait_group 1;"  ::: "memory"); }

__device__ __forceinline__ void ldsm4(uint32_t* r, uint32_t a) {
    asm volatile("ldmatrix.sync.aligned.m8n8.x4.shared.b16 {%0,%1,%2,%3}, [%4];"
        : "=r"(r[0]),"=r"(r[1]),"=r"(r[2]),"=r"(r[3]) : "r"(a));
}
__device__ __forceinline__ void ldsm4t(uint32_t* r, uint32_t a) {
    asm volatile("ldmatrix.sync.aligned.m8n8.x4.trans.shared.b16 {%0,%1,%2,%3}, [%4];"
        : "=r"(r[0]),"=r"(r[1]),"=r"(r[2]),"=r"(r[3]) : "r"(a));
}
// fp16 MMA
__device__ __forceinline__ void mma16816h(float* c, const uint32_t* a, const uint32_t* b) {
    asm volatile("mma.sync.aligned.m16n8k16.row.col.f32.f16.f16.f32 "
        "{%0,%1,%2,%3}, {%4,%5,%6,%7}, {%8,%9}, {%0,%1,%2,%3};"
        : "+f"(c[0]),"+f"(c[1]),"+f"(c[2]),"+f"(c[3])
        : "r"(a[0]),"r"(a[1]),"r"(a[2]),"r"(a[3]), "r"(b[0]),"r"(b[1]));
}
__device__ __forceinline__ uint32_t pack2h(float x, float y) {
    __half2 t = __floats2half2_rn(x, y);
    return *(uint32_t*)&t;
}
__device__ __forceinline__ float hhi(float v) {
    return __half2float(__float2half_rn(v));
}
__device__ __forceinline__ void f2hlh(float v, __half& h, __half& l) {
    h = __float2half_rn(v);
    l = __float2half_rn(v - __half2float(h));
}
__device__ __forceinline__ float ex2f(float x) {
    float y; asm("ex2.approx.f32 %0, %1;" : "=f"(y) : "f"(x)); return y;
}

// ---------------------------------------------------------------------------
// LayerNorm -> fp16 hi/lo
// ---------------------------------------------------------------------------
__global__ void ln_split_kernel(const float* __restrict__ x,
                                const float* __restrict__ gamma,
                                const float* __restrict__ beta,
                                __half* __restrict__ xh, __half* __restrict__ xl) {
    const int row = blockIdx.x;
    const int t   = threadIdx.x;
    float4 v = ((const float4*)(x + (size_t)row * DIM))[t];
    float s  = v.x + v.y + v.z + v.w;
    float sq = v.x*v.x + v.y*v.y + v.z*v.z + v.w*v.w;
    #pragma unroll
    for (int o = 16; o > 0; o >>= 1) {
        s  += __shfl_down_sync(0xffffffffu, s,  o);
        sq += __shfl_down_sync(0xffffffffu, sq, o);
    }
    __shared__ float ws[8], wq[8], s_mu, s_rstd;
    const int lane = t & 31, wid = t >> 5;
    if (lane == 0) { ws[wid] = s; wq[wid] = sq; }
    __syncthreads();
    if (t == 0) {
        float S = 0.f, Q = 0.f;
        #pragma unroll
        for (int i = 0; i < 8; i++) { S += ws[i]; Q += wq[i]; }
        float mu = S * (1.0f / DIM);
        float var = Q * (1.0f / DIM) - mu * mu;
        s_mu = mu; s_rstd = rsqrtf(var + LN_EPS);
    }
    __syncthreads();
    const float mu = s_mu, rstd = s_rstd;
    float4 g = ((const float4*)gamma)[t];
    float4 b = ((const float4*)beta)[t];
    float y0 = (v.x-mu)*rstd*g.x + b.x, y1 = (v.y-mu)*rstd*g.y + b.y;
    float y2 = (v.z-mu)*rstd*g.z + b.z, y3 = (v.w-mu)*rstd*g.w + b.w;
    __half h0,h1,h2,h3,l0,l1,l2,l3;
    f2hlh(y0,h0,l0); f2hlh(y1,h1,l1); f2hlh(y2,h2,l2); f2hlh(y3,h3,l3);
    __half2* H = (__half2*)(xh + (size_t)row * DIM);
    __half2* L = (__half2*)(xl + (size_t)row * DIM);
    H[2*t]   = __halves2half2(h0,h1);  H[2*t+1] = __halves2half2(h2,h3);
    L[2*t]   = __halves2half2(l0,l1);  L[2*t+1] = __halves2half2(l2,l3);
}

// ---------------------------------------------------------------------------
// W[K][N] f32 -> WT [N][K] single fp16
// ---------------------------------------------------------------------------
__global__ void transpose_kernel(const float* __restrict__ W,
                                 __half* __restrict__ Th,
                                 int Kd, int Nd) {
    __shared__ float t[32][33];
    const int n0 = blockIdx.x * 32, k0 = blockIdx.y * 32;
    const int tx = threadIdx.x, ty = threadIdx.y;
    #pragma unroll
    for (int i = 0; i < 32; i += 8)
        t[ty + i][tx] = W[(size_t)(k0 + ty + i) * Nd + n0 + tx];
    __syncthreads();
    #pragma unroll
    for (int i = 0; i < 32; i += 8) {
        const size_t idx = (size_t)(n0 + ty + i) * Kd + k0 + tx;
        Th[idx] = __float2half_rn(t[tx][ty + i]);
    }
}

// ---------------------------------------------------------------------------
// 2-MMA fp16 GEMM: C = (Ah + Al) * B, A-split fp16 (22-bit), B single fp16.
// 128x128 tile, BK=64. Stage = Ah+Al+B = 48KB; 2 stages = 96KB -> 2 CTAs/SM
// WITH depth-1 cp.async double buffering (R12-attention pipeline pattern).
// ---------------------------------------------------------------------------
#define GBK      64
#define GREG_B   16384             // one region: 128 rows x 128B
#define GSTAGE_B (3*GREG_B)        // 48KB: Ah, Al, B
#define GNC      (KD / GBK)        // 16 chunks
#define GEMM_SMEM (2*GSTAGE_B)     // 98304

template<int EPI>
__global__ void __launch_bounds__(256, 2)
gemm_mma_kernel(const __half* __restrict__ Ah, const __half* __restrict__ Al,
                const __half* __restrict__ B,
                __half* __restrict__ qh, __half* __restrict__ kh, __half* __restrict__ vh,
                const float* __restrict__ bias, float* __restrict__ outf) {
    extern __shared__ char smem[];
    const uint32_t sb = smem_u32(smem);
    const int tid = threadIdx.x;
    const int w = tid >> 5, lane = tid & 31;
    const int wm = w >> 2, wn = w & 3;
    const int brow = blockIdx.y * 128;
    const int bcol = blockIdx.x * 128;

    // Loader: 8 threads per 128B row (proven R8 geometry)
    const int lrow = tid >> 3, lc = tid & 7;
    const uint32_t ldst = SWZ128(lrow * 128 + lc * 16);
    const __half* gp0 = Ah + (size_t)(brow + lrow) * KD + lc * 8;
    const __half* gp1 = Al + (size_t)(brow + lrow) * KD + lc * 8;
    const __half* gp2 = B  + (size_t)(bcol + lrow) * KD + lc * 8;

    auto load_chunk = [&](int stage, int ch) {
        const uint32_t bb = sb + stage * GSTAGE_B;
        const size_t ko = (size_t)ch * GBK;
        #pragma unroll
        for (int sub = 0; sub < 4; sub++) {
            const uint32_t d = ldst + sub * 4096;
            const size_t go = (size_t)sub * 32 * KD + ko;
            cp16(bb + 0*GREG_B + d, gp0 + go);
            cp16(bb + 1*GREG_B + d, gp1 + go);
            cp16(bb + 2*GREG_B + d, gp2 + go);
        }
    };

    // Fragment bases
    const int grp = lane >> 3, r8 = lane & 7;
    uint32_t aSwz[4], bSwz[2];
    #pragma unroll
    for (int mf = 0; mf < 4; mf++) {
        const int arow = wm*64 + mf*16 + (lane & 15);
        aSwz[mf] = SWZ128(arow * 128) ^ ((lane >> 4) << 4);
    }
    #pragma unroll
    for (int bt = 0; bt < 2; bt++) {
        const int brw = wn*32 + bt*16 + r8 + ((grp & 2) ? 8 : 0);
        bSwz[bt] = SWZ128(brw * 128) ^ ((grp & 1) ? 16 : 0);
    }

    float acc[4][4][4] = {};

    load_chunk(0, 0); cp_commit();

    for (int ch = 0; ch < GNC; ch++) {
        if (ch + 1 < GNC) load_chunk((ch + 1) & 1, ch + 1);
        cp_commit();
        if (ch + 1 < GNC) cp_wait1(); else cp_wait0();
        __syncthreads();
        const uint32_t bb = sb + (ch & 1) * GSTAGE_B;

        #pragma unroll
        for (int ks = 0; ks < 4; ks++) {
            uint32_t Bf[2][4];
            #pragma unroll
            for (int bt = 0; bt < 2; bt++)
                ldsm4(Bf[bt], bb + 2*GREG_B + (bSwz[bt] ^ (ks * 32)));
            #pragma unroll
            for (int mf = 0; mf < 4; mf++) {
                uint32_t Ah4[4], Al4[4];
                const uint32_t ad = bb + (aSwz[mf] ^ (ks * 32));
                ldsm4(Ah4, ad);
                ldsm4(Al4, ad + GREG_B);
                #pragma unroll
                for (int nf = 0; nf < 4; nf++) {
                    const uint32_t* b2 = &Bf[nf >> 1][(nf & 1) * 2];
                    mma16816h(acc[mf][nf], Ah4, b2);
                    mma16816h(acc[mf][nf], Al4, b2);
                }
            }
        }
        __syncthreads();   // compute done before this stage is overwritten (ch+2)
    }

    const int t4 = lane >> 2, t2 = (lane & 3) * 2;
    if (EPI == 0) {
        const int part = bcol >> 10;
        __half* dst = (part == 0) ? qh : (part == 1) ? kh : vh;
        #pragma unroll
        for (int mf = 0; mf < 4; mf++) {
            #pragma unroll
            for (int nf = 0; nf < 4; nf++) {
                const int c0 = bcol + wn*32 + nf*8 + t2;
                const int inner = c0 & 1023;
                const int hh_ = inner >> 6, d = inner & 63;
                #pragma unroll
                for (int rr = 0; rr < 2; rr++) {
                    const int m = brow + wm*64 + mf*16 + t4 + rr*8;
                    const int bq = m >> 11, n = m & 2047;
                    const size_t idx = (((size_t)(bq*HH + hh_))*NN + n)*DH + d;
                    *(uint32_t*)(dst + idx) = pack2h(acc[mf][nf][rr*2], acc[mf][nf][rr*2+1]);
                }
            }
        }
    } else {
        #pragma unroll
        for (int mf = 0; mf < 4; mf++) {
            #pragma unroll
            for (int nf = 0; nf < 4; nf++) {
                const int c0 = bcol + wn*32 + nf*8 + t2;
                #pragma unroll
                for (int rr = 0; rr < 2; rr++) {
                    const int m = brow + wm*64 + mf*16 + t4 + rr*8;
                    float2 o2;
                    o2.x = acc[mf][nf][rr*2]   + bias[c0];
                    o2.y = acc[mf][nf][rr*2+1] + bias[c0+1];
                    *(float2*)(outf + (size_t)m * DIM + c0) = o2;
                }
            }
        }
    }
}

// ---------------------------------------------------------------------------
// Attention: FA2-style fp16 (unchanged from R12 except fp16 hi/lo output).
// KV stage 16KB double-buffered = 32KB; Q register-resident. 2 CTAs/SM.
// ---------------------------------------------------------------------------
#define ATILE_B   8192               // K or V: 64 rows x 128B
#define ASTAGE_B  (2*ATILE_B)        // 16KB: K,V
#define ATTN_SMEM (2*ASTAGE_B)       // 32768

__global__ void __launch_bounds__(256, 2)
attn_mma_kernel(const __half* __restrict__ Q, const __half* __restrict__ K,
                const __half* __restrict__ V,
                __half* __restrict__ Ohi, __half* __restrict__ Olo) {
    extern __shared__ char smem[];
    const uint32_t sb = smem_u32(smem);
    const int tid = threadIdx.x;
    const int w = tid >> 5, lane = tid & 31;
    const int grp = lane >> 3, r8 = lane & 7;
    const int qt = blockIdx.x, hh_ = blockIdx.y, bq = blockIdx.z;
    const size_t hb = ((size_t)(bq*HH + hh_)) * NN * DH;

    const int lrow = tid >> 3, lc = tid & 7;
    const uint32_t ldst = SWZ128(lrow * 128 + lc * 16);

    // ---- Stage Q tile (128 x 64 fp16 = 16KB) transiently in stage 0 ----
    {
        const __half* qs = Q + hb + (size_t)qt*128*DH + lc*8;
        #pragma unroll
        for (int s = 0; s < 4; s++)
            cp16(sb + ldst + s*4096, qs + (size_t)(lrow + s*32) * DH);
        cp_commit(); cp_wait0();
    }
    __syncthreads();
    const int qrow = w*16 + (lane & 15);
    const uint32_t rb = SWZ128(qrow * 128) ^ ((lane >> 4) << 4);
    uint32_t qf[4][4];
    #pragma unroll
    for (int ks = 0; ks < 4; ks++) ldsm4(qf[ks], sb + (rb ^ (ks * 32)));
    __syncthreads();   // Q extracted; stage 0 may be overwritten

    uint32_t kSwz[4];
    #pragma unroll
    for (int p = 0; p < 4; p++) {
        const int brw = p*16 + r8 + ((grp & 2) ? 8 : 0);
        kSwz[p] = SWZ128(brw * 128) ^ ((grp & 1) ? 16 : 0);
    }
    const int vrsub = r8 + ((grp & 1) ? 8 : 0);
    const uint32_t vcoff = (grp & 2) ? 16 : 0;

    const __half* kp = K + hb + (size_t)lrow * DH + lc*8;
    const __half* vp = V + hb + (size_t)lrow * DH + lc*8;

    auto load_tile = [&](int stage, int t) {
        const uint32_t bb = sb + stage * ASTAGE_B;
        const size_t tb = (size_t)t * 64 * DH;
        #pragma unroll
        for (int sub = 0; sub < 2; sub++) {
            const uint32_t d = ldst + sub * 4096;
            const size_t go = tb + (size_t)sub * 32 * DH;
            cp16(bb + d,           kp + go);
            cp16(bb + ATILE_B + d, vp + go);
        }
    };

    float oacc[8][4] = {};
    float dsum0 = 0.f, dsum1 = 0.f;

    load_tile(0, 0); cp_commit();

    for (int t = 0; t < NN/64; t++) {
        if (t + 1 < NN/64) load_tile((t + 1) & 1, t + 1);
        cp_commit();
        cp_wait1();
        __syncthreads();
        const uint32_t bb = sb + (t & 1) * ASTAGE_B;

        float sacc[8][4] = {};
        #pragma unroll
        for (int ks = 0; ks < 4; ks++) {
            #pragma unroll
            for (int p = 0; p < 4; p++) {
                uint32_t Kf[4];
                ldsm4(Kf, bb + (kSwz[p] ^ (ks * 32)));
                mma16816h(sacc[2*p+0], qf[ks], &Kf[0]);
                mma16816h(sacc[2*p+1], qf[ks], &Kf[2]);
            }
        }

        #pragma unroll
        for (int j = 0; j < 4; j++) {
            float pA[4], pB[4];
            #pragma unroll
            for (int e = 0; e < 4; e++) pA[e] = ex2f(sacc[2*j][e]   * SCL2E);
            #pragma unroll
            for (int e = 0; e < 4; e++) pB[e] = ex2f(sacc[2*j+1][e] * SCL2E);
            dsum0 += pA[0] + pA[1] + pB[0] + pB[1];
            dsum1 += pA[2] + pA[3] + pB[2] + pB[3];
            uint32_t pf[4];
            pf[0] = pack2h(pA[0], pA[1]);  pf[1] = pack2h(pA[2], pA[3]);
            pf[2] = pack2h(pB[0], pB[1]);  pf[3] = pack2h(pB[2], pB[3]);
            const int vrow = j*16 + vrsub;
            const uint32_t vb = SWZ128(vrow * 128) ^ vcoff;
            #pragma unroll
            for (int p = 0; p < 4; p++) {
                uint32_t Vf[4];
                ldsm4t(Vf, bb + ATILE_B + (vb ^ (p * 32)));
                mma16816h(oacc[2*p+0], pf, &Vf[0]);
                mma16816h(oacc[2*p+1], pf, &Vf[2]);
            }
        }
        __syncthreads();
    }

    dsum0 += __shfl_xor_sync(0xffffffffu, dsum0, 1);
    dsum0 += __shfl_xor_sync(0xffffffffu, dsum0, 2);
    dsum1 += __shfl_xor_sync(0xffffffffu, dsum1, 1);
    dsum1 += __shfl_xor_sync(0xffffffffu, dsum1, 2);
    const float inv0 = 1.0f / (dsum0 + ATTN_EPS);
    const float inv1 = 1.0f / (dsum1 + ATTN_EPS);

    const int t4 = lane >> 2, t2 = (lane & 3) * 2;
    #pragma unroll
    for (int nf = 0; nf < 8; nf++) {
        const int d = nf*8 + t2;
        const int n0 = qt*128 + w*16 + t4;
        float v00 = oacc[nf][0]*inv0, v01 = oacc[nf][1]*inv0;
        float v10 = oacc[nf][2]*inv1, v11 = oacc[nf][3]*inv1;
        const size_t i0 = ((size_t)(bq*NN + n0)    )*INNER + hh_*DH + d;
        const size_t i1 = ((size_t)(bq*NN + n0 + 8))*INNER + hh_*DH + d;
        *(uint32_t*)(Ohi + i0) = pack2h(v00, v01);
        *(uint32_t*)(Olo + i0) = pack2h(v00 - hhi(v00), v01 - hhi(v01));
        *(uint32_t*)(Ohi + i1) = pack2h(v10, v11);
        *(uint32_t*)(Olo + i1) = pack2h(v10 - hhi(v10), v11 - hhi(v11));
    }
}

// ---------------------------------------------------------------------------
extern "C" void kernel_launch(void* const* d_in, const int* in_sizes, int n_in,
                              void* d_out, int out_size) {
    const float* x      = (const float*)d_in[0];
    const float* gamma  = (const float*)d_in[1];
    const float* beta   = (const float*)d_in[2];
    const float* w_qkv  = (const float*)d_in[3];
    const float* w_out  = (const float*)d_in[4];
    const float* b_out  = (const float*)d_in[5];
    float* out = (float*)d_out;

    __half *xh,*xl,*wq,*wo,*q,*k,*v,*oh,*ol;
    cudaGetSymbolAddress((void**)&xh, g_xn_hi);
    cudaGetSymbolAddress((void**)&xl, g_xn_lo);
    cudaGetSymbolAddress((void**)&wq, g_wqT);
    cudaGetSymbolAddress((void**)&wo, g_woT);
    cudaGetSymbolAddress((void**)&q,  g_q);
    cudaGetSymbolAddress((void**)&k,  g_k);
    cudaGetSymbolAddress((void**)&v,  g_v);
    cudaGetSymbolAddress((void**)&oh, g_o_hi);
    cudaGetSymbolAddress((void**)&ol, g_o_lo);

    cudaFuncSetAttribute(gemm_mma_kernel<0>, cudaFuncAttributeMaxDynamicSharedMemorySize, GEMM_SMEM);
    cudaFuncSetAttribute(gemm_mma_kernel<1>, cudaFuncAttributeMaxDynamicSharedMemorySize, GEMM_SMEM);
    cudaFuncSetAttribute(attn_mma_kernel,    cudaFuncAttributeMaxDynamicSharedMemorySize, ATTN_SMEM);

    ln_split_kernel<<<ROWS, 256>>>(x, gamma, beta, xh, xl);
    transpose_kernel<<<dim3(NQKV/32, KD/32), dim3(32, 8)>>>(w_qkv, wq, KD, NQKV);
    transpose_kernel<<<dim3(DIM/32,  KD/32), dim3(32, 8)>>>(w_out, wo, KD, DIM);
    gemm_mma_kernel<0><<<dim3(NQKV/128, ROWS/128), 256, GEMM_SMEM>>>(
        xh, xl, wq, q, k, v, nullptr, nullptr);
    attn_mma_kernel<<<dim3(NN/128, HH, BB), 256, ATTN_SMEM>>>(q, k, v, oh, ol);
    gemm_mma_kernel<1><<<dim3(DIM/128, ROWS/128), 256, GEMM_SMEM>>>(
        oh, ol, wo, nullptr, nullptr, nullptr, b_out, out);
}

// round 14
// speedup vs baseline: 3.3534x; 1.0776x over previous
#include <cuda_runtime.h>
#include <cuda_bf16.h>
#include <cuda_fp16.h>
#include <math.h>
#include <stdint.h>

#define BB     2
#define NN     2048
#define DIM    1024
#define HH     16
#define DH     64
#define INNER  1024
#define ROWS   (BB*NN)       // 4096
#define NQKV   3072
#define KD     1024
#define LN_EPS   1e-5f
#define ATTN_EPS 1e-8f
#define SCALE    0.125f
#define SCL2E    0.1803368801111244f   // SCALE * log2(e)

// ---------------------------------------------------------------------------
// Scratch (device globals)
// ---------------------------------------------------------------------------
__device__ __half g_xn_hi[ROWS * DIM];
__device__ __half g_xn_lo[ROWS * DIM];
__device__ __half g_wqT[NQKV * KD];
__device__ __half g_woT[DIM * KD];
__device__ __half g_q[BB*HH*NN*DH];
__device__ __half g_k[BB*HH*NN*DH];
__device__ __half g_v[BB*HH*NN*DH];
__device__ __half g_o[ROWS * INNER];   // single fp16 now (split dropped)

// ---------------------------------------------------------------------------
// Helpers
// ---------------------------------------------------------------------------
__device__ __forceinline__ uint32_t smem_u32(const void* p) {
    uint32_t a;
    asm("{ .reg .u64 t; cvta.to.shared.u64 t, %1; cvt.u32.u64 %0, t; }" : "=r"(a) : "l"(p));
    return a;
}
#define SWZ128(x) ((x) ^ (((x) >> 3) & 0x70))

__device__ __forceinline__ void cp16(uint32_t dst, const void* src) {
    size_t g = __cvta_generic_to_global(src);
    asm volatile("cp.async.cg.shared.global [%0], [%1], 16;" :: "r"(dst), "l"(g) : "memory");
}
__device__ __forceinline__ void cp_commit() { asm volatile("cp.async.commit_group;" ::: "memory"); }
__device__ __forceinline__ void cp_wait0()  { asm volatile("cp.async.wait_group 0;"  ::: "memory"); }
__device__ __forceinline__ void cp_wait1()  { asm volatile("cp.async.wait_group 1;"  ::: "memory"); }

__device__ __forceinline__ void ldsm4(uint32_t* r, uint32_t a) {
    asm volatile("ldmatrix.sync.aligned.m8n8.x4.shared.b16 {%0,%1,%2,%3}, [%4];"
        : "=r"(r[0]),"=r"(r[1]),"=r"(r[2]),"=r"(r[3]) : "r"(a));
}
__device__ __forceinline__ void ldsm4t(uint32_t* r, uint32_t a) {
    asm volatile("ldmatrix.sync.aligned.m8n8.x4.trans.shared.b16 {%0,%1,%2,%3}, [%4];"
        : "=r"(r[0]),"=r"(r[1]),"=r"(r[2]),"=r"(r[3]) : "r"(a));
}
__device__ __forceinline__ void mma16816h(float* c, const uint32_t* a, const uint32_t* b) {
    asm volatile("mma.sync.aligned.m16n8k16.row.col.f32.f16.f16.f32 "
        "{%0,%1,%2,%3}, {%4,%5,%6,%7}, {%8,%9}, {%0,%1,%2,%3};"
        : "+f"(c[0]),"+f"(c[1]),"+f"(c[2]),"+f"(c[3])
        : "r"(a[0]),"r"(a[1]),"r"(a[2]),"r"(a[3]), "r"(b[0]),"r"(b[1]));
}
__device__ __forceinline__ uint32_t pack2h(float x, float y) {
    __half2 t = __floats2half2_rn(x, y);
    return *(uint32_t*)&t;
}
__device__ __forceinline__ void f2hlh(float v, __half& h, __half& l) {
    h = __float2half_rn(v);
    l = __float2half_rn(v - __half2float(h));
}
__device__ __forceinline__ float ex2f(float x) {
    float y; asm("ex2.approx.f32 %0, %1;" : "=f"(y) : "f"(x)); return y;
}

// ---------------------------------------------------------------------------
// LayerNorm -> fp16 hi/lo
// ---------------------------------------------------------------------------
__global__ void ln_split_kernel(const float* __restrict__ x,
                                const float* __restrict__ gamma,
                                const float* __restrict__ beta,
                                __half* __restrict__ xh, __half* __restrict__ xl) {
    const int row = blockIdx.x;
    const int t   = threadIdx.x;
    float4 v = ((const float4*)(x + (size_t)row * DIM))[t];
    float s  = v.x + v.y + v.z + v.w;
    float sq = v.x*v.x + v.y*v.y + v.z*v.z + v.w*v.w;
    #pragma unroll
    for (int o = 16; o > 0; o >>= 1) {
        s  += __shfl_down_sync(0xffffffffu, s,  o);
        sq += __shfl_down_sync(0xffffffffu, sq, o);
    }
    __shared__ float ws[8], wq[8], s_mu, s_rstd;
    const int lane = t & 31, wid = t >> 5;
    if (lane == 0) { ws[wid] = s; wq[wid] = sq; }
    __syncthreads();
    if (t == 0) {
        float S = 0.f, Q = 0.f;
        #pragma unroll
        for (int i = 0; i < 8; i++) { S += ws[i]; Q += wq[i]; }
        float mu = S * (1.0f / DIM);
        float var = Q * (1.0f / DIM) - mu * mu;
        s_mu = mu; s_rstd = rsqrtf(var + LN_EPS);
    }
    __syncthreads();
    const float mu = s_mu, rstd = s_rstd;
    float4 g = ((const float4*)gamma)[t];
    float4 b = ((const float4*)beta)[t];
    float y0 = (v.x-mu)*rstd*g.x + b.x, y1 = (v.y-mu)*rstd*g.y + b.y;
    float y2 = (v.z-mu)*rstd*g.z + b.z, y3 = (v.w-mu)*rstd*g.w + b.w;
    __half h0,h1,h2,h3,l0,l1,l2,l3;
    f2hlh(y0,h0,l0); f2hlh(y1,h1,l1); f2hlh(y2,h2,l2); f2hlh(y3,h3,l3);
    __half2* H = (__half2*)(xh + (size_t)row * DIM);
    __half2* L = (__half2*)(xl + (size_t)row * DIM);
    H[2*t]   = __halves2half2(h0,h1);  H[2*t+1] = __halves2half2(h2,h3);
    L[2*t]   = __halves2half2(l0,l1);  L[2*t+1] = __halves2half2(l2,l3);
}

// ---------------------------------------------------------------------------
// W[K][N] f32 -> WT [N][K] single fp16
// ---------------------------------------------------------------------------
__global__ void transpose_kernel(const float* __restrict__ W,
                                 __half* __restrict__ Th,
                                 int Kd, int Nd) {
    __shared__ float t[32][33];
    const int n0 = blockIdx.x * 32, k0 = blockIdx.y * 32;
    const int tx = threadIdx.x, ty = threadIdx.y;
    #pragma unroll
    for (int i = 0; i < 32; i += 8)
        t[ty + i][tx] = W[(size_t)(k0 + ty + i) * Nd + n0 + tx];
    __syncthreads();
    #pragma unroll
    for (int i = 0; i < 32; i += 8) {
        const size_t idx = (size_t)(n0 + ty + i) * Kd + k0 + tx;
        Th[idx] = __float2half_rn(t[tx][ty + i]);
    }
}

// ---------------------------------------------------------------------------
// fp16 GEMM, 128x128 tile, BK=64, 2-stage cp.async, 2 CTAs/SM.
// EPI 0 (QKV): A split hi/lo (2 MMA), writes q/k/v fp16 [b,h,n,d].
// EPI 1 (out): A single (1 MMA),  +bias, f32 out. Stage shrinks to 32KB.
// ---------------------------------------------------------------------------
#define GBK      64
#define GREG_B   16384             // one region: 128 rows x 128B
#define GNC      (KD / GBK)        // 16 chunks

template<int EPI>
__global__ void __launch_bounds__(256, 2)
gemm_mma_kernel(const __half* __restrict__ Ah, const __half* __restrict__ Al,
                const __half* __restrict__ B,
                __half* __restrict__ qh, __half* __restrict__ kh, __half* __restrict__ vh,
                const float* __restrict__ bias, float* __restrict__ outf) {
    constexpr int NREG = (EPI == 0) ? 3 : 2;           // Ah[,Al],B regions
    constexpr uint32_t STAGE_B = NREG * GREG_B;
    extern __shared__ char smem[];
    const uint32_t sb = smem_u32(smem);
    const int tid = threadIdx.x;
    const int w = tid >> 5, lane = tid & 31;
    const int wm = w >> 2, wn = w & 3;
    const int brow = blockIdx.y * 128;
    const int bcol = blockIdx.x * 128;

    const int lrow = tid >> 3, lc = tid & 7;
    const uint32_t ldst = SWZ128(lrow * 128 + lc * 16);
    const __half* gp0 = Ah + (size_t)(brow + lrow) * KD + lc * 8;
    const __half* gp1 = (EPI == 0) ? (Al + (size_t)(brow + lrow) * KD + lc * 8) : nullptr;
    const __half* gpB = B + (size_t)(bcol + lrow) * KD + lc * 8;

    auto load_chunk = [&](int stage, int ch) {
        const uint32_t bb = sb + stage * STAGE_B;
        const size_t ko = (size_t)ch * GBK;
        #pragma unroll
        for (int sub = 0; sub < 4; sub++) {
            const uint32_t d = ldst + sub * 4096;
            const size_t go = (size_t)sub * 32 * KD + ko;
            cp16(bb + d, gp0 + go);
            if (EPI == 0) cp16(bb + GREG_B + d, gp1 + go);
            cp16(bb + (NREG - 1) * GREG_B + d, gpB + go);
        }
    };

    const int grp = lane >> 3, r8 = lane & 7;
    uint32_t aSwz[4], bSwz[2];
    #pragma unroll
    for (int mf = 0; mf < 4; mf++) {
        const int arow = wm*64 + mf*16 + (lane & 15);
        aSwz[mf] = SWZ128(arow * 128) ^ ((lane >> 4) << 4);
    }
    #pragma unroll
    for (int bt = 0; bt < 2; bt++) {
        const int brw = wn*32 + bt*16 + r8 + ((grp & 2) ? 8 : 0);
        bSwz[bt] = SWZ128(brw * 128) ^ ((grp & 1) ? 16 : 0);
    }

    float acc[4][4][4] = {};

    load_chunk(0, 0); cp_commit();

    for (int ch = 0; ch < GNC; ch++) {
        if (ch + 1 < GNC) load_chunk((ch + 1) & 1, ch + 1);
        cp_commit();
        if (ch + 1 < GNC) cp_wait1(); else cp_wait0();
        __syncthreads();
        const uint32_t bb = sb + (ch & 1) * STAGE_B;

        #pragma unroll
        for (int ks = 0; ks < 4; ks++) {
            uint32_t Bf[2][4];
            #pragma unroll
            for (int bt = 0; bt < 2; bt++)
                ldsm4(Bf[bt], bb + (NREG - 1) * GREG_B + (bSwz[bt] ^ (ks * 32)));
            #pragma unroll
            for (int mf = 0; mf < 4; mf++) {
                uint32_t Ah4[4], Al4[4];
                const uint32_t ad = bb + (aSwz[mf] ^ (ks * 32));
                ldsm4(Ah4, ad);
                if (EPI == 0) ldsm4(Al4, ad + GREG_B);
                #pragma unroll
                for (int nf = 0; nf < 4; nf++) {
                    const uint32_t* b2 = &Bf[nf >> 1][(nf & 1) * 2];
                    mma16816h(acc[mf][nf], Ah4, b2);
                    if (EPI == 0) mma16816h(acc[mf][nf], Al4, b2);
                }
            }
        }
        __syncthreads();
    }

    const int t4 = lane >> 2, t2 = (lane & 3) * 2;
    if (EPI == 0) {
        const int part = bcol >> 10;
        __half* dst = (part == 0) ? qh : (part == 1) ? kh : vh;
        #pragma unroll
        for (int mf = 0; mf < 4; mf++) {
            #pragma unroll
            for (int nf = 0; nf < 4; nf++) {
                const int c0 = bcol + wn*32 + nf*8 + t2;
                const int inner = c0 & 1023;
                const int hh_ = inner >> 6, d = inner & 63;
                #pragma unroll
                for (int rr = 0; rr < 2; rr++) {
                    const int m = brow + wm*64 + mf*16 + t4 + rr*8;
                    const int bq = m >> 11, n = m & 2047;
                    const size_t idx = (((size_t)(bq*HH + hh_))*NN + n)*DH + d;
                    *(uint32_t*)(dst + idx) = pack2h(acc[mf][nf][rr*2], acc[mf][nf][rr*2+1]);
                }
            }
        }
    } else {
        #pragma unroll
        for (int mf = 0; mf < 4; mf++) {
            #pragma unroll
            for (int nf = 0; nf < 4; nf++) {
                const int c0 = bcol + wn*32 + nf*8 + t2;
                #pragma unroll
                for (int rr = 0; rr < 2; rr++) {
                    const int m = brow + wm*64 + mf*16 + t4 + rr*8;
                    float2 o2;
                    o2.x = acc[mf][nf][rr*2]   + bias[c0];
                    o2.y = acc[mf][nf][rr*2+1] + bias[c0+1];
                    *(float2*)(outf + (size_t)m * DIM + c0) = o2;
                }
            }
        }
    }
}
#define GEMM_SMEM0 (2 * 3 * GREG_B)   // 98304
#define GEMM_SMEM1 (2 * 2 * GREG_B)   // 65536

// ---------------------------------------------------------------------------
// Attention: FA2-style fp16 (R13 structure). Single fp16 O output.
// ---------------------------------------------------------------------------
#define ATILE_B   8192
#define ASTAGE_B  (2*ATILE_B)        // 16KB: K,V
#define ATTN_SMEM (2*ASTAGE_B)       // 32768

__global__ void __launch_bounds__(256, 2)
attn_mma_kernel(const __half* __restrict__ Q, const __half* __restrict__ K,
                const __half* __restrict__ V, __half* __restrict__ O) {
    extern __shared__ char smem[];
    const uint32_t sb = smem_u32(smem);
    const int tid = threadIdx.x;
    const int w = tid >> 5, lane = tid & 31;
    const int grp = lane >> 3, r8 = lane & 7;
    const int qt = blockIdx.x, hh_ = blockIdx.y, bq = blockIdx.z;
    const size_t hb = ((size_t)(bq*HH + hh_)) * NN * DH;

    const int lrow = tid >> 3, lc = tid & 7;
    const uint32_t ldst = SWZ128(lrow * 128 + lc * 16);

    {
        const __half* qs = Q + hb + (size_t)qt*128*DH + lc*8;
        #pragma unroll
        for (int s = 0; s < 4; s++)
            cp16(sb + ldst + s*4096, qs + (size_t)(lrow + s*32) * DH);
        cp_commit(); cp_wait0();
    }
    __syncthreads();
    const int qrow = w*16 + (lane & 15);
    const uint32_t rb = SWZ128(qrow * 128) ^ ((lane >> 4) << 4);
    uint32_t qf[4][4];
    #pragma unroll
    for (int ks = 0; ks < 4; ks++) ldsm4(qf[ks], sb + (rb ^ (ks * 32)));
    __syncthreads();

    uint32_t kSwz[4];
    #pragma unroll
    for (int p = 0; p < 4; p++) {
        const int brw = p*16 + r8 + ((grp & 2) ? 8 : 0);
        kSwz[p] = SWZ128(brw * 128) ^ ((grp & 1) ? 16 : 0);
    }
    const int vrsub = r8 + ((grp & 1) ? 8 : 0);
    const uint32_t vcoff = (grp & 2) ? 16 : 0;

    const __half* kp = K + hb + (size_t)lrow * DH + lc*8;
    const __half* vp = V + hb + (size_t)lrow * DH + lc*8;

    auto load_tile = [&](int stage, int t) {
        const uint32_t bb = sb + stage * ASTAGE_B;
        const size_t tb = (size_t)t * 64 * DH;
        #pragma unroll
        for (int sub = 0; sub < 2; sub++) {
            const uint32_t d = ldst + sub * 4096;
            const size_t go = tb + (size_t)sub * 32 * DH;
            cp16(bb + d,           kp + go);
            cp16(bb + ATILE_B + d, vp + go);
        }
    };

    float oacc[8][4] = {};
    float dsum0 = 0.f, dsum1 = 0.f;

    load_tile(0, 0); cp_commit();

    for (int t = 0; t < NN/64; t++) {
        if (t + 1 < NN/64) load_tile((t + 1) & 1, t + 1);
        cp_commit();
        cp_wait1();
        __syncthreads();
        const uint32_t bb = sb + (t & 1) * ASTAGE_B;

        float sacc[8][4] = {};
        #pragma unroll
        for (int ks = 0; ks < 4; ks++) {
            #pragma unroll
            for (int p = 0; p < 4; p++) {
                uint32_t Kf[4];
                ldsm4(Kf, bb + (kSwz[p] ^ (ks * 32)));
                mma16816h(sacc[2*p+0], qf[ks], &Kf[0]);
                mma16816h(sacc[2*p+1], qf[ks], &Kf[2]);
            }
        }

        #pragma unroll
        for (int j = 0; j < 4; j++) {
            float pA[4], pB[4];
            #pragma unroll
            for (int e = 0; e < 4; e++) pA[e] = ex2f(sacc[2*j][e]   * SCL2E);
            #pragma unroll
            for (int e = 0; e < 4; e++) pB[e] = ex2f(sacc[2*j+1][e] * SCL2E);
            dsum0 += pA[0] + pA[1] + pB[0] + pB[1];
            dsum1 += pA[2] + pA[3] + pB[2] + pB[3];
            uint32_t pf[4];
            pf[0] = pack2h(pA[0], pA[1]);  pf[1] = pack2h(pA[2], pA[3]);
            pf[2] = pack2h(pB[0], pB[1]);  pf[3] = pack2h(pB[2], pB[3]);
            const int vrow = j*16 + vrsub;
            const uint32_t vb = SWZ128(vrow * 128) ^ vcoff;
            #pragma unroll
            for (int p = 0; p < 4; p++) {
                uint32_t Vf[4];
                ldsm4t(Vf, bb + ATILE_B + (vb ^ (p * 32)));
                mma16816h(oacc[2*p+0], pf, &Vf[0]);
                mma16816h(oacc[2*p+1], pf, &Vf[2]);
            }
        }
        __syncthreads();
    }

    dsum0 += __shfl_xor_sync(0xffffffffu, dsum0, 1);
    dsum0 += __shfl_xor_sync(0xffffffffu, dsum0, 2);
    dsum1 += __shfl_xor_sync(0xffffffffu, dsum1, 1);
    dsum1 += __shfl_xor_sync(0xffffffffu, dsum1, 2);
    const float inv0 = 1.0f / (dsum0 + ATTN_EPS);
    const float inv1 = 1.0f / (dsum1 + ATTN_EPS);

    const int t4 = lane >> 2, t2 = (lane & 3) * 2;
    #pragma unroll
    for (int nf = 0; nf < 8; nf++) {
        const int d = nf*8 + t2;
        const int n0 = qt*128 + w*16 + t4;
        const size_t i0 = ((size_t)(bq*NN + n0)    )*INNER + hh_*DH + d;
        const size_t i1 = ((size_t)(bq*NN + n0 + 8))*INNER + hh_*DH + d;
        *(uint32_t*)(O + i0) = pack2h(oacc[nf][0]*inv0, oacc[nf][1]*inv0);
        *(uint32_t*)(O + i1) = pack2h(oacc[nf][2]*inv1, oacc[nf][3]*inv1);
    }
}

// ---------------------------------------------------------------------------
extern "C" void kernel_launch(void* const* d_in, const int* in_sizes, int n_in,
                              void* d_out, int out_size) {
    const float* x      = (const float*)d_in[0];
    const float* gamma  = (const float*)d_in[1];
    const float* beta   = (const float*)d_in[2];
    const float* w_qkv  = (const float*)d_in[3];
    const float* w_out  = (const float*)d_in[4];
    const float* b_out  = (const float*)d_in[5];
    float* out = (float*)d_out;

    __half *xh,*xl,*wq,*wo,*q,*k,*v,*o;
    cudaGetSymbolAddress((void**)&xh, g_xn_hi);
    cudaGetSymbolAddress((void**)&xl, g_xn_lo);
    cudaGetSymbolAddress((void**)&wq, g_wqT);
    cudaGetSymbolAddress((void**)&wo, g_woT);
    cudaGetSymbolAddress((void**)&q,  g_q);
    cudaGetSymbolAddress((void**)&k,  g_k);
    cudaGetSymbolAddress((void**)&v,  g_v);
    cudaGetSymbolAddress((void**)&o,  g_o);

    cudaFuncSetAttribute(gemm_mma_kernel<0>, cudaFuncAttributeMaxDynamicSharedMemorySize, GEMM_SMEM0);
    cudaFuncSetAttribute(gemm_mma_kernel<1>, cudaFuncAttributeMaxDynamicSharedMemorySize, GEMM_SMEM1);
    cudaFuncSetAttribute(attn_mma_kernel,    cudaFuncAttributeMaxDynamicSharedMemorySize, ATTN_SMEM);

    ln_split_kernel<<<ROWS, 256>>>(x, gamma, beta, xh, xl);
    transpose_kernel<<<dim3(NQKV/32, KD/32), dim3(32, 8)>>>(w_qkv, wq, KD, NQKV);
    transpose_kernel<<<dim3(DIM/32,  KD/32), dim3(32, 8)>>>(w_out, wo, KD, DIM);
    gemm_mma_kernel<0><<<dim3(NQKV/128, ROWS/128), 256, GEMM_SMEM0>>>(
        xh, xl, wq, q, k, v, nullptr, nullptr);
    attn_mma_kernel<<<dim3(NN/128, HH, BB), 256, ATTN_SMEM>>>(q, k, v, o);
    gemm_mma_kernel<1><<<dim3(DIM/128, ROWS/128), 256, GEMM_SMEM1>>>(
        o, nullptr, wo, nullptr, nullptr, nullptr, b_out, out);
}

// round 15
// speedup vs baseline: 4.1595x; 1.2404x over previous
#include <cuda_runtime.h>
#include <cuda_bf16.h>
#include <cuda_fp16.h>
#include <math.h>
#include <stdint.h>

#define BB     2
#define NN     2048
#define DIM    1024
#define HH     16
#define DH     64
#define INNER  1024
#define ROWS   (BB*NN)       // 4096
#define NQKV   3072
#define KD     1024
#define LN_EPS   1e-5f
#define ATTN_EPS 1e-8f
#define SCALE    0.125f
#define SCL2E    0.1803368801111244f   // SCALE * log2(e)

// ---------------------------------------------------------------------------
// Scratch (device globals) — everything single fp16 now
// ---------------------------------------------------------------------------
__device__ __half g_xn[ROWS * DIM];
__device__ __half g_wqT[NQKV * KD];
__device__ __half g_woT[DIM * KD];
__device__ __half g_q[BB*HH*NN*DH];
__device__ __half g_k[BB*HH*NN*DH];
__device__ __half g_v[BB*HH*NN*DH];
__device__ __half g_o[ROWS * INNER];

// ---------------------------------------------------------------------------
// Helpers
// ---------------------------------------------------------------------------
__device__ __forceinline__ uint32_t smem_u32(const void* p) {
    uint32_t a;
    asm("{ .reg .u64 t; cvta.to.shared.u64 t, %1; cvt.u32.u64 %0, t; }" : "=r"(a) : "l"(p));
    return a;
}
#define SWZ128(x) ((x) ^ (((x) >> 3) & 0x70))

__device__ __forceinline__ void cp16(uint32_t dst, const void* src) {
    size_t g = __cvta_generic_to_global(src);
    asm volatile("cp.async.cg.shared.global [%0], [%1], 16;" :: "r"(dst), "l"(g) : "memory");
}
__device__ __forceinline__ void cp_commit() { asm volatile("cp.async.commit_group;" ::: "memory"); }
__device__ __forceinline__ void cp_wait0()  { asm volatile("cp.async.wait_group 0;"  ::: "memory"); }
__device__ __forceinline__ void cp_wait1()  { asm volatile("cp.async.wait_group 1;"  ::: "memory"); }

__device__ __forceinline__ void ldsm4(uint32_t* r, uint32_t a) {
    asm volatile("ldmatrix.sync.aligned.m8n8.x4.shared.b16 {%0,%1,%2,%3}, [%4];"
        : "=r"(r[0]),"=r"(r[1]),"=r"(r[2]),"=r"(r[3]) : "r"(a));
}
__device__ __forceinline__ void ldsm4t(uint32_t* r, uint32_t a) {
    asm volatile("ldmatrix.sync.aligned.m8n8.x4.trans.shared.b16 {%0,%1,%2,%3}, [%4];"
        : "=r"(r[0]),"=r"(r[1]),"=r"(r[2]),"=r"(r[3]) : "r"(a));
}
__device__ __forceinline__ void mma16816h(float* c, const uint32_t* a, const uint32_t* b) {
    asm volatile("mma.sync.aligned.m16n8k16.row.col.f32.f16.f16.f32 "
        "{%0,%1,%2,%3}, {%4,%5,%6,%7}, {%8,%9}, {%0,%1,%2,%3};"
        : "+f"(c[0]),"+f"(c[1]),"+f"(c[2]),"+f"(c[3])
        : "r"(a[0]),"r"(a[1]),"r"(a[2]),"r"(a[3]), "r"(b[0]),"r"(b[1]));
}
__device__ __forceinline__ uint32_t pack2h(float x, float y) {
    __half2 t = __floats2half2_rn(x, y);
    return *(uint32_t*)&t;
}
__device__ __forceinline__ float ex2f(float x) {
    float y; asm("ex2.approx.f32 %0, %1;" : "=f"(y) : "f"(x)); return y;
}

// ---------------------------------------------------------------------------
// LayerNorm -> single fp16
// ---------------------------------------------------------------------------
__global__ void ln_kernel(const float* __restrict__ x,
                          const float* __restrict__ gamma,
                          const float* __restrict__ beta,
                          __half* __restrict__ xn) {
    const int row = blockIdx.x;
    const int t   = threadIdx.x;
    float4 v = ((const float4*)(x + (size_t)row * DIM))[t];
    float s  = v.x + v.y + v.z + v.w;
    float sq = v.x*v.x + v.y*v.y + v.z*v.z + v.w*v.w;
    #pragma unroll
    for (int o = 16; o > 0; o >>= 1) {
        s  += __shfl_down_sync(0xffffffffu, s,  o);
        sq += __shfl_down_sync(0xffffffffu, sq, o);
    }
    __shared__ float ws[8], wq[8], s_mu, s_rstd;
    const int lane = t & 31, wid = t >> 5;
    if (lane == 0) { ws[wid] = s; wq[wid] = sq; }
    __syncthreads();
    if (t == 0) {
        float S = 0.f, Q = 0.f;
        #pragma unroll
        for (int i = 0; i < 8; i++) { S += ws[i]; Q += wq[i]; }
        float mu = S * (1.0f / DIM);
        float var = Q * (1.0f / DIM) - mu * mu;
        s_mu = mu; s_rstd = rsqrtf(var + LN_EPS);
    }
    __syncthreads();
    const float mu = s_mu, rstd = s_rstd;
    float4 g = ((const float4*)gamma)[t];
    float4 b = ((const float4*)beta)[t];
    float y0 = (v.x-mu)*rstd*g.x + b.x, y1 = (v.y-mu)*rstd*g.y + b.y;
    float y2 = (v.z-mu)*rstd*g.z + b.z, y3 = (v.w-mu)*rstd*g.w + b.w;
    __half2* H = (__half2*)(xn + (size_t)row * DIM);
    H[2*t]   = __floats2half2_rn(y0, y1);
    H[2*t+1] = __floats2half2_rn(y2, y3);
}

// ---------------------------------------------------------------------------
// W[K][N] f32 -> WT [N][K] single fp16
// ---------------------------------------------------------------------------
__global__ void transpose_kernel(const float* __restrict__ W,
                                 __half* __restrict__ Th,
                                 int Kd, int Nd) {
    __shared__ float t[32][33];
    const int n0 = blockIdx.x * 32, k0 = blockIdx.y * 32;
    const int tx = threadIdx.x, ty = threadIdx.y;
    #pragma unroll
    for (int i = 0; i < 32; i += 8)
        t[ty + i][tx] = W[(size_t)(k0 + ty + i) * Nd + n0 + tx];
    __syncthreads();
    #pragma unroll
    for (int i = 0; i < 32; i += 8) {
        const size_t idx = (size_t)(n0 + ty + i) * Kd + k0 + tx;
        Th[idx] = __float2half_rn(t[tx][ty + i]);
    }
}

// ---------------------------------------------------------------------------
// Single-fp16 GEMM: 128x128 tile, BK=64, 2-stage cp.async, 2 CTAs/SM.
// Stage = A(16KB)+B(16KB) = 32KB; 2 stages = 64KB.
// EPI 0: write q/k/v fp16 [b,h,n,d]. EPI 1: +bias, f32 out.
// ---------------------------------------------------------------------------
#define GBK      64
#define GREG_B   16384             // one region: 128 rows x 128B
#define GSTAGE_B (2*GREG_B)        // 32KB: A, B
#define GNC      (KD / GBK)        // 16 chunks
#define GEMM_SMEM (2*GSTAGE_B)     // 65536

template<int EPI>
__global__ void __launch_bounds__(256, 2)
gemm_mma_kernel(const __half* __restrict__ A, const __half* __restrict__ B,
                __half* __restrict__ qh, __half* __restrict__ kh, __half* __restrict__ vh,
                const float* __restrict__ bias, float* __restrict__ outf) {
    extern __shared__ char smem[];
    const uint32_t sb = smem_u32(smem);
    const int tid = threadIdx.x;
    const int w = tid >> 5, lane = tid & 31;
    const int wm = w >> 2, wn = w & 3;
    const int brow = blockIdx.y * 128;
    const int bcol = blockIdx.x * 128;

    const int lrow = tid >> 3, lc = tid & 7;
    const uint32_t ldst = SWZ128(lrow * 128 + lc * 16);
    const __half* gpA = A + (size_t)(brow + lrow) * KD + lc * 8;
    const __half* gpB = B + (size_t)(bcol + lrow) * KD + lc * 8;

    auto load_chunk = [&](int stage, int ch) {
        const uint32_t bb = sb + stage * GSTAGE_B;
        const size_t ko = (size_t)ch * GBK;
        #pragma unroll
        for (int sub = 0; sub < 4; sub++) {
            const uint32_t d = ldst + sub * 4096;
            const size_t go = (size_t)sub * 32 * KD + ko;
            cp16(bb + d,          gpA + go);
            cp16(bb + GREG_B + d, gpB + go);
        }
    };

    const int grp = lane >> 3, r8 = lane & 7;
    uint32_t aSwz[4], bSwz[2];
    #pragma unroll
    for (int mf = 0; mf < 4; mf++) {
        const int arow = wm*64 + mf*16 + (lane & 15);
        aSwz[mf] = SWZ128(arow * 128) ^ ((lane >> 4) << 4);
    }
    #pragma unroll
    for (int bt = 0; bt < 2; bt++) {
        const int brw = wn*32 + bt*16 + r8 + ((grp & 2) ? 8 : 0);
        bSwz[bt] = SWZ128(brw * 128) ^ ((grp & 1) ? 16 : 0);
    }

    float acc[4][4][4] = {};

    load_chunk(0, 0); cp_commit();

    for (int ch = 0; ch < GNC; ch++) {
        if (ch + 1 < GNC) load_chunk((ch + 1) & 1, ch + 1);
        cp_commit();
        if (ch + 1 < GNC) cp_wait1(); else cp_wait0();
        __syncthreads();
        const uint32_t bb = sb + (ch & 1) * GSTAGE_B;

        #pragma unroll
        for (int ks = 0; ks < 4; ks++) {
            uint32_t Bf[2][4];
            #pragma unroll
            for (int bt = 0; bt < 2; bt++)
                ldsm4(Bf[bt], bb + GREG_B + (bSwz[bt] ^ (ks * 32)));
            #pragma unroll
            for (int mf = 0; mf < 4; mf++) {
                uint32_t A4[4];
                ldsm4(A4, bb + (aSwz[mf] ^ (ks * 32)));
                #pragma unroll
                for (int nf = 0; nf < 4; nf++)
                    mma16816h(acc[mf][nf], A4, &Bf[nf >> 1][(nf & 1) * 2]);
            }
        }
        __syncthreads();
    }

    const int t4 = lane >> 2, t2 = (lane & 3) * 2;
    if (EPI == 0) {
        const int part = bcol >> 10;
        __half* dst = (part == 0) ? qh : (part == 1) ? kh : vh;
        #pragma unroll
        for (int mf = 0; mf < 4; mf++) {
            #pragma unroll
            for (int nf = 0; nf < 4; nf++) {
                const int c0 = bcol + wn*32 + nf*8 + t2;
                const int inner = c0 & 1023;
                const int hh_ = inner >> 6, d = inner & 63;
                #pragma unroll
                for (int rr = 0; rr < 2; rr++) {
                    const int m = brow + wm*64 + mf*16 + t4 + rr*8;
                    const int bq = m >> 11, n = m & 2047;
                    const size_t idx = (((size_t)(bq*HH + hh_))*NN + n)*DH + d;
                    *(uint32_t*)(dst + idx) = pack2h(acc[mf][nf][rr*2], acc[mf][nf][rr*2+1]);
                }
            }
        }
    } else {
        #pragma unroll
        for (int mf = 0; mf < 4; mf++) {
            #pragma unroll
            for (int nf = 0; nf < 4; nf++) {
                const int c0 = bcol + wn*32 + nf*8 + t2;
                #pragma unroll
                for (int rr = 0; rr < 2; rr++) {
                    const int m = brow + wm*64 + mf*16 + t4 + rr*8;
                    float2 o2;
                    o2.x = acc[mf][nf][rr*2]   + bias[c0];
                    o2.y = acc[mf][nf][rr*2+1] + bias[c0+1];
                    *(float2*)(outf + (size_t)m * DIM + c0) = o2;
                }
            }
        }
    }
}

// ---------------------------------------------------------------------------
// Attention: FA2-style fp16 (unchanged from R14).
// ---------------------------------------------------------------------------
#define ATILE_B   8192
#define ASTAGE_B  (2*ATILE_B)        // 16KB: K,V
#define ATTN_SMEM (2*ASTAGE_B)       // 32768

__global__ void __launch_bounds__(256, 2)
attn_mma_kernel(const __half* __restrict__ Q, const __half* __restrict__ K,
                const __half* __restrict__ V, __half* __restrict__ O) {
    extern __shared__ char smem[];
    const uint32_t sb = smem_u32(smem);
    const int tid = threadIdx.x;
    const int w = tid >> 5, lane = tid & 31;
    const int grp = lane >> 3, r8 = lane & 7;
    const int qt = blockIdx.x, hh_ = blockIdx.y, bq = blockIdx.z;
    const size_t hb = ((size_t)(bq*HH + hh_)) * NN * DH;

    const int lrow = tid >> 3, lc = tid & 7;
    const uint32_t ldst = SWZ128(lrow * 128 + lc * 16);

    {
        const __half* qs = Q + hb + (size_t)qt*128*DH + lc*8;
        #pragma unroll
        for (int s = 0; s < 4; s++)
            cp16(sb + ldst + s*4096, qs + (size_t)(lrow + s*32) * DH);
        cp_commit(); cp_wait0();
    }
    __syncthreads();
    const int qrow = w*16 + (lane & 15);
    const uint32_t rb = SWZ128(qrow * 128) ^ ((lane >> 4) << 4);
    uint32_t qf[4][4];
    #pragma unroll
    for (int ks = 0; ks < 4; ks++) ldsm4(qf[ks], sb + (rb ^ (ks * 32)));
    __syncthreads();

    uint32_t kSwz[4];
    #pragma unroll
    for (int p = 0; p < 4; p++) {
        const int brw = p*16 + r8 + ((grp & 2) ? 8 : 0);
        kSwz[p] = SWZ128(brw * 128) ^ ((grp & 1) ? 16 : 0);
    }
    const int vrsub = r8 + ((grp & 1) ? 8 : 0);
    const uint32_t vcoff = (grp & 2) ? 16 : 0;

    const __half* kp = K + hb + (size_t)lrow * DH + lc*8;
    const __half* vp = V + hb + (size_t)lrow * DH + lc*8;

    auto load_tile = [&](int stage, int t) {
        const uint32_t bb = sb + stage * ASTAGE_B;
        const size_t tb = (size_t)t * 64 * DH;
        #pragma unroll
        for (int sub = 0; sub < 2; sub++) {
            const uint32_t d = ldst + sub * 4096;
            const size_t go = tb + (size_t)sub * 32 * DH;
            cp16(bb + d,           kp + go);
            cp16(bb + ATILE_B + d, vp + go);
        }
    };

    float oacc[8][4] = {};
    float dsum0 = 0.f, dsum1 = 0.f;

    load_tile(0, 0); cp_commit();

    for (int t = 0; t < NN/64; t++) {
        if (t + 1 < NN/64) load_tile((t + 1) & 1, t + 1);
        cp_commit();
        cp_wait1();
        __syncthreads();
        const uint32_t bb = sb + (t & 1) * ASTAGE_B;

        float sacc[8][4] = {};
        #pragma unroll
        for (int ks = 0; ks < 4; ks++) {
            #pragma unroll
            for (int p = 0; p < 4; p++) {
                uint32_t Kf[4];
                ldsm4(Kf, bb + (kSwz[p] ^ (ks * 32)));
                mma16816h(sacc[2*p+0], qf[ks], &Kf[0]);
                mma16816h(sacc[2*p+1], qf[ks], &Kf[2]);
            }
        }

        #pragma unroll
        for (int j = 0; j < 4; j++) {
            float pA[4], pB[4];
            #pragma unroll
            for (int e = 0; e < 4; e++) pA[e] = ex2f(sacc[2*j][e]   * SCL2E);
            #pragma unroll
            for (int e = 0; e < 4; e++) pB[e] = ex2f(sacc[2*j+1][e] * SCL2E);
            dsum0 += pA[0] + pA[1] + pB[0] + pB[1];
            dsum1 += pA[2] + pA[3] + pB[2] + pB[3];
            uint32_t pf[4];
            pf[0] = pack2h(pA[0], pA[1]);  pf[1] = pack2h(pA[2], pA[3]);
            pf[2] = pack2h(pB[0], pB[1]);  pf[3] = pack2h(pB[2], pB[3]);
            const int vrow = j*16 + vrsub;
            const uint32_t vb = SWZ128(vrow * 128) ^ vcoff;
            #pragma unroll
            for (int p = 0; p < 4; p++) {
                uint32_t Vf[4];
                ldsm4t(Vf, bb + ATILE_B + (vb ^ (p * 32)));
                mma16816h(oacc[2*p+0], pf, &Vf[0]);
                mma16816h(oacc[2*p+1], pf, &Vf[2]);
            }
        }
        __syncthreads();
    }

    dsum0 += __shfl_xor_sync(0xffffffffu, dsum0, 1);
    dsum0 += __shfl_xor_sync(0xffffffffu, dsum0, 2);
    dsum1 += __shfl_xor_sync(0xffffffffu, dsum1, 1);
    dsum1 += __shfl_xor_sync(0xffffffffu, dsum1, 2);
    const float inv0 = 1.0f / (dsum0 + ATTN_EPS);
    const float inv1 = 1.0f / (dsum1 + ATTN_EPS);

    const int t4 = lane >> 2, t2 = (lane & 3) * 2;
    #pragma unroll
    for (int nf = 0; nf < 8; nf++) {
        const int d = nf*8 + t2;
        const int n0 = qt*128 + w*16 + t4;
        const size_t i0 = ((size_t)(bq*NN + n0)    )*INNER + hh_*DH + d;
        const size_t i1 = ((size_t)(bq*NN + n0 + 8))*INNER + hh_*DH + d;
        *(uint32_t*)(O + i0) = pack2h(oacc[nf][0]*inv0, oacc[nf][1]*inv0);
        *(uint32_t*)(O + i1) = pack2h(oacc[nf][2]*inv1, oacc[nf][3]*inv1);
    }
}

// ---------------------------------------------------------------------------
extern "C" void kernel_launch(void* const* d_in, const int* in_sizes, int n_in,
                              void* d_out, int out_size) {
    const float* x      = (const float*)d_in[0];
    const float* gamma  = (const float*)d_in[1];
    const float* beta   = (const float*)d_in[2];
    const float* w_qkv  = (const float*)d_in[3];
    const float* w_out  = (const float*)d_in[4];
    const float* b_out  = (const float*)d_in[5];
    float* out = (float*)d_out;

    __half *xn,*wq,*wo,*q,*k,*v,*o;
    cudaGetSymbolAddress((void**)&xn, g_xn);
    cudaGetSymbolAddress((void**)&wq, g_wqT);
    cudaGetSymbolAddress((void**)&wo, g_woT);
    cudaGetSymbolAddress((void**)&q,  g_q);
    cudaGetSymbolAddress((void**)&k,  g_k);
    cudaGetSymbolAddress((void**)&v,  g_v);
    cudaGetSymbolAddress((void**)&o,  g_o);

    cudaFuncSetAttribute(gemm_mma_kernel<0>, cudaFuncAttributeMaxDynamicSharedMemorySize, GEMM_SMEM);
    cudaFuncSetAttribute(gemm_mma_kernel<1>, cudaFuncAttributeMaxDynamicSharedMemorySize, GEMM_SMEM);
    cudaFuncSetAttribute(attn_mma_kernel,    cudaFuncAttributeMaxDynamicSharedMemorySize, ATTN_SMEM);

    ln_kernel<<<ROWS, 256>>>(x, gamma, beta, xn);
    transpose_kernel<<<dim3(NQKV/32, KD/32), dim3(32, 8)>>>(w_qkv, wq, KD, NQKV);
    transpose_kernel<<<dim3(DIM/32,  KD/32), dim3(32, 8)>>>(w_out, wo, KD, DIM);
    gemm_mma_kernel<0><<<dim3(NQKV/128, ROWS/128), 256, GEMM_SMEM>>>(
        xn, wq, q, k, v, nullptr, nullptr);
    attn_mma_kernel<<<dim3(NN/128, HH, BB), 256, ATTN_SMEM>>>(q, k, v, o);
    gemm_mma_kernel<1><<<dim3(DIM/128, ROWS/128), 256, GEMM_SMEM>>>(
        o, wo, nullptr, nullptr, nullptr, b_out, out);
}